// round 1
// baseline (speedup 1.0000x reference)
#include <cuda_runtime.h>
#include <cstdint>

#define NN 50000
#define EE 800000
#define DD 128
#define HH 8

// ---------------- scratch (static device allocations; no cudaMalloc) --------
__device__ float g_Q [(size_t)NN * DD];
__device__ float g_K [(size_t)NN * DD];
__device__ float g_V [(size_t)NN * DD];
__device__ float g_P [(size_t)EE * DD];   // proj_e
__device__ float g_EO[(size_t)EE * DD];   // e_out (= e_attn)
__device__ float g_wV[(size_t)NN * DD];
__device__ float g_z [(size_t)NN * HH];

// packed fp32x2 FMA (Blackwell FFMA2; 2x fp32 FMA throughput)
__device__ __forceinline__ void ffma2(float2 &acc, float2 a, float2 b) {
    unsigned long long *cp = reinterpret_cast<unsigned long long *>(&acc);
    unsigned long long *ap = reinterpret_cast<unsigned long long *>(&a);
    unsigned long long *bp = reinterpret_cast<unsigned long long *>(&b);
    asm volatile("fma.rn.f32x2 %0, %1, %2, %0;" : "+l"(*cp) : "l"(*ap), "l"(*bp));
}

__device__ __forceinline__ float comp4(const float4 &v, int kk) {
    return reinterpret_cast<const float *>(&v)[kk];
}

// ---------------------------------------------------------------------------
// Generic Y[R x 128] = (optional LN(X)) @ W[128 x 128] + bias (+ resid)
// Block: 64 rows x 128 cols, 256 threads, W fully in smem, fp32x2 math.
// ---------------------------------------------------------------------------
__global__ void __launch_bounds__(256) gemm128(
    const float *__restrict__ X,
    const float *__restrict__ lnw, const float *__restrict__ lnb,
    const float *__restrict__ W, const float *__restrict__ bias,
    const float *__restrict__ resid,
    float *__restrict__ Y, int R)
{
    extern __shared__ float sm[];
    float *Xs = sm;               // [64][128]
    float *Ws = sm + 64 * DD;     // [128][128]
    const int tid  = threadIdx.x;
    const int row0 = blockIdx.x * 64;

    // load W (16384 floats)
    {
        const float4 *W4  = reinterpret_cast<const float4 *>(W);
        float4       *Ws4 = reinterpret_cast<float4 *>(Ws);
        #pragma unroll
        for (int i = 0; i < 16; i++) Ws4[tid + 256 * i] = W4[tid + 256 * i];
    }
    // load X tile (4 threads/row, 32 floats each) + optional LayerNorm
    {
        const int r     = tid >> 2;
        const int cpart = (tid & 3) * 32;
        const int grow  = row0 + r;
        float4 v[8];
        if (grow < R) {
            const float4 *Xr = reinterpret_cast<const float4 *>(X + (size_t)grow * DD + cpart);
            #pragma unroll
            for (int i = 0; i < 8; i++) v[i] = Xr[i];
        } else {
            #pragma unroll
            for (int i = 0; i < 8; i++) v[i] = make_float4(0.f, 0.f, 0.f, 0.f);
        }
        if (lnw) {
            float s = 0.f, ss = 0.f;
            #pragma unroll
            for (int i = 0; i < 8; i++) {
                s  += v[i].x + v[i].y + v[i].z + v[i].w;
                ss += v[i].x * v[i].x + v[i].y * v[i].y + v[i].z * v[i].z + v[i].w * v[i].w;
            }
            s  += __shfl_xor_sync(0xffffffffu, s, 1);
            s  += __shfl_xor_sync(0xffffffffu, s, 2);
            ss += __shfl_xor_sync(0xffffffffu, ss, 1);
            ss += __shfl_xor_sync(0xffffffffu, ss, 2);
            const float m   = s * (1.f / DD);
            const float var = ss * (1.f / DD) - m * m;
            const float rs  = rsqrtf(var + 1e-5f);
            #pragma unroll
            for (int i = 0; i < 8; i++) {
                const int c = cpart + 4 * i;
                v[i].x = (v[i].x - m) * rs * lnw[c + 0] + lnb[c + 0];
                v[i].y = (v[i].y - m) * rs * lnw[c + 1] + lnb[c + 1];
                v[i].z = (v[i].z - m) * rs * lnw[c + 2] + lnb[c + 2];
                v[i].w = (v[i].w - m) * rs * lnw[c + 3] + lnb[c + 3];
            }
        }
        float4 *Xw = reinterpret_cast<float4 *>(Xs + r * DD + cpart);
        #pragma unroll
        for (int i = 0; i < 8; i++) Xw[i] = v[i];
    }
    __syncthreads();

    const int cg = tid & 31;   // cols cg + 32j
    const int rg = tid >> 5;   // rows rg + 8i
    float2 acc[4][4];
    #pragma unroll
    for (int t = 0; t < 4; t++)
        #pragma unroll
        for (int j = 0; j < 4; j++) acc[t][j] = make_float2(0.f, 0.f);

    #pragma unroll 2
    for (int k0 = 0; k0 < DD; k0 += 4) {
        float4 xq[8];
        #pragma unroll
        for (int i = 0; i < 8; i++)
            xq[i] = *reinterpret_cast<const float4 *>(Xs + (rg + 8 * i) * DD + k0);
        #pragma unroll
        for (int kk = 0; kk < 4; kk++) {
            float2 wd[4];
            #pragma unroll
            for (int j = 0; j < 4; j++) {
                const float w = Ws[(k0 + kk) * DD + cg + 32 * j];
                wd[j] = make_float2(w, w);
            }
            #pragma unroll
            for (int t = 0; t < 4; t++) {
                // pair rows (rg+16t, rg+16t+8)
                float2 xp = make_float2(comp4(xq[2 * t], kk), comp4(xq[2 * t + 1], kk));
                #pragma unroll
                for (int j = 0; j < 4; j++) ffma2(acc[t][j], xp, wd[j]);
            }
        }
    }

    #pragma unroll
    for (int t = 0; t < 4; t++) {
        const int rA = row0 + rg + 16 * t;
        const int rB = rA + 8;
        #pragma unroll
        for (int j = 0; j < 4; j++) {
            const int c = cg + 32 * j;
            const float b = bias ? bias[c] : 0.f;
            if (rA < R) {
                float o = acc[t][j].x + b;
                if (resid) o += resid[(size_t)rA * DD + c];
                Y[(size_t)rA * DD + c] = o;
            }
            if (rB < R) {
                float o = acc[t][j].y + b;
                if (resid) o += resid[(size_t)rB * DD + c];
                Y[(size_t)rB * DD + c] = o;
            }
        }
    }
}

// ---------------------------------------------------------------------------
// Per-edge attention: score = clip(K[src]*Q[dst]/4), e_out = score*P,
// w = exp(clip(sum_head e_out)), scatter wV += V[src]*w, z += w.
// One warp per edge; lane handles 4 contiguous elems (within one head).
// ---------------------------------------------------------------------------
__global__ void __launch_bounds__(256) edge_attn(
    const float *__restrict__ K, const float *__restrict__ Q,
    const float *__restrict__ V, const float *__restrict__ P,
    const int *__restrict__ src, const int *__restrict__ dst,
    float *__restrict__ eout, float *__restrict__ wV, float *__restrict__ z)
{
    const int e = blockIdx.x * 8 + (threadIdx.x >> 5);
    if (e >= EE) return;
    const int lane = threadIdx.x & 31;
    const int s = src[e];
    const int d = dst[e];

    const float4 kv = reinterpret_cast<const float4 *>(K + (size_t)s * DD)[lane];
    const float4 qv = reinterpret_cast<const float4 *>(Q + (size_t)d * DD)[lane];
    const float4 pv = reinterpret_cast<const float4 *>(P + (size_t)e * DD)[lane];

    float4 eo;
    eo.x = fminf(fmaxf(kv.x * qv.x * 0.25f, -5.f), 5.f) * pv.x;
    eo.y = fminf(fmaxf(kv.y * qv.y * 0.25f, -5.f), 5.f) * pv.y;
    eo.z = fminf(fmaxf(kv.z * qv.z * 0.25f, -5.f), 5.f) * pv.z;
    eo.w = fminf(fmaxf(kv.w * qv.w * 0.25f, -5.f), 5.f) * pv.w;
    reinterpret_cast<float4 *>(eout + (size_t)e * DD)[lane] = eo;

    float ps = eo.x + eo.y + eo.z + eo.w;       // 4 of the 16 elems of head lane/4
    ps += __shfl_xor_sync(0xffffffffu, ps, 1);
    ps += __shfl_xor_sync(0xffffffffu, ps, 2);
    const float w = __expf(fminf(fmaxf(ps, -5.f), 5.f));

    const float4 vv = reinterpret_cast<const float4 *>(V + (size_t)s * DD)[lane];
    float *wvp = wV + (size_t)d * DD + lane * 4;
    atomicAdd(wvp + 0, vv.x * w);
    atomicAdd(wvp + 1, vv.y * w);
    atomicAdd(wvp + 2, vv.z * w);
    atomicAdd(wvp + 3, vv.w * w);
    if ((lane & 3) == 0) atomicAdd(z + (size_t)d * HH + (lane >> 2), w);
}

__global__ void __launch_bounds__(256) attn_norm(float *__restrict__ wV,
                                                 const float *__restrict__ z)
{
    const int i = blockIdx.x * 256 + threadIdx.x;
    if (i < NN * DD) {
        const int n = i >> 7;
        const int c = i & 127;
        wV[i] = wV[i] / (z[(size_t)n * HH + (c >> 4)] + 1e-8f);
    }
}

// ---------------------------------------------------------------------------
// Fused LN2 + MLP (silu(x@W1)@W2) + residual, in place on Y rows.
// Block: 32 rows, 256 threads. W streamed in 64KB chunks -> 2 blocks/SM.
// ---------------------------------------------------------------------------
__global__ void __launch_bounds__(256) mlp128(
    float *__restrict__ Y,
    const float *__restrict__ lnw, const float *__restrict__ lnb,
    const float *__restrict__ W1, const float *__restrict__ W2, int R)
{
    extern __shared__ float sm[];
    float *Xs = sm;                         // [32][128]
    float *Hs = sm + 32 * 128;              // [32][256]
    float *Ws = sm + 32 * 128 + 32 * 256;   // [128][128] chunk
    const int tid  = threadIdx.x;
    const int row0 = blockIdx.x * 32;

    // load rows + LayerNorm (8 threads/row, 16 floats each)
    {
        const int r     = tid >> 3;
        const int cpart = (tid & 7) * 16;
        const int grow  = row0 + r;
        float4 v[4];
        if (grow < R) {
            const float4 *Xr = reinterpret_cast<const float4 *>(Y + (size_t)grow * DD + cpart);
            #pragma unroll
            for (int i = 0; i < 4; i++) v[i] = Xr[i];
        } else {
            #pragma unroll
            for (int i = 0; i < 4; i++) v[i] = make_float4(0.f, 0.f, 0.f, 0.f);
        }
        float s = 0.f, ss = 0.f;
        #pragma unroll
        for (int i = 0; i < 4; i++) {
            s  += v[i].x + v[i].y + v[i].z + v[i].w;
            ss += v[i].x * v[i].x + v[i].y * v[i].y + v[i].z * v[i].z + v[i].w * v[i].w;
        }
        s  += __shfl_xor_sync(0xffffffffu, s, 1);
        s  += __shfl_xor_sync(0xffffffffu, s, 2);
        s  += __shfl_xor_sync(0xffffffffu, s, 4);
        ss += __shfl_xor_sync(0xffffffffu, ss, 1);
        ss += __shfl_xor_sync(0xffffffffu, ss, 2);
        ss += __shfl_xor_sync(0xffffffffu, ss, 4);
        const float m   = s * (1.f / DD);
        const float var = ss * (1.f / DD) - m * m;
        const float rs  = rsqrtf(var + 1e-5f);
        #pragma unroll
        for (int i = 0; i < 4; i++) {
            const int c = cpart + 4 * i;
            v[i].x = (v[i].x - m) * rs * lnw[c + 0] + lnb[c + 0];
            v[i].y = (v[i].y - m) * rs * lnw[c + 1] + lnb[c + 1];
            v[i].z = (v[i].z - m) * rs * lnw[c + 2] + lnb[c + 2];
            v[i].w = (v[i].w - m) * rs * lnw[c + 3] + lnb[c + 3];
        }
        float4 *Xw = reinterpret_cast<float4 *>(Xs + r * DD + cpart);
        #pragma unroll
        for (int i = 0; i < 4; i++) Xw[i] = v[i];
    }

    const int cg = tid & 31;   // col group
    const int rg = tid >> 5;   // row group: rows rg + 8i

    // ---- phase 1: hidden[32][256] = silu(Xs @ W1), 2 column chunks --------
    for (int ch = 0; ch < 2; ch++) {
        __syncthreads();
        // load W1[:, ch*128 : ch*128+128] -> Ws[k][cc]
        {
            #pragma unroll
            for (int i = 0; i < 16; i++) {
                const int f  = (tid + 256 * i) * 4;  // flat float index in chunk
                const int k  = f >> 7;
                const int cc = f & 127;
                *reinterpret_cast<float4 *>(Ws + f) =
                    *reinterpret_cast<const float4 *>(W1 + (size_t)k * 256 + ch * 128 + cc);
            }
        }
        __syncthreads();
        float2 acc[2][4];
        #pragma unroll
        for (int t = 0; t < 2; t++)
            #pragma unroll
            for (int j = 0; j < 4; j++) acc[t][j] = make_float2(0.f, 0.f);

        #pragma unroll 2
        for (int k0 = 0; k0 < 128; k0 += 4) {
            float4 xq[4];
            #pragma unroll
            for (int i = 0; i < 4; i++)
                xq[i] = *reinterpret_cast<const float4 *>(Xs + (rg + 8 * i) * 128 + k0);
            #pragma unroll
            for (int kk = 0; kk < 4; kk++) {
                float2 wd[4];
                #pragma unroll
                for (int j = 0; j < 4; j++) {
                    const float w = Ws[(k0 + kk) * 128 + cg + 32 * j];
                    wd[j] = make_float2(w, w);
                }
                #pragma unroll
                for (int t = 0; t < 2; t++) {
                    float2 xp = make_float2(comp4(xq[2 * t], kk), comp4(xq[2 * t + 1], kk));
                    #pragma unroll
                    for (int j = 0; j < 4; j++) ffma2(acc[t][j], xp, wd[j]);
                }
            }
        }
        // silu + store to Hs
        #pragma unroll
        for (int t = 0; t < 2; t++) {
            const int rA = rg + 16 * t;
            const int rB = rA + 8;
            #pragma unroll
            for (int j = 0; j < 4; j++) {
                const int c = ch * 128 + cg + 32 * j;
                float a = acc[t][j].x;
                Hs[rA * 256 + c] = a / (1.f + __expf(-a));
                a = acc[t][j].y;
                Hs[rB * 256 + c] = a / (1.f + __expf(-a));
            }
        }
    }

    // ---- phase 2: out[32][128] = Hs @ W2 (+ residual), 2 k-chunks ---------
    float2 acc[2][4];
    #pragma unroll
    for (int t = 0; t < 2; t++)
        #pragma unroll
        for (int j = 0; j < 4; j++) acc[t][j] = make_float2(0.f, 0.f);

    for (int ch = 0; ch < 2; ch++) {
        __syncthreads();
        // load W2 rows [ch*128, ch*128+128) (contiguous 16384 floats)
        {
            const float4 *W4  = reinterpret_cast<const float4 *>(W2 + (size_t)ch * 128 * 128);
            float4       *Ws4 = reinterpret_cast<float4 *>(Ws);
            #pragma unroll
            for (int i = 0; i < 16; i++) Ws4[tid + 256 * i] = W4[tid + 256 * i];
        }
        __syncthreads();
        #pragma unroll 2
        for (int k0 = 0; k0 < 128; k0 += 4) {
            float4 hq[4];
            #pragma unroll
            for (int i = 0; i < 4; i++)
                hq[i] = *reinterpret_cast<const float4 *>(Hs + (rg + 8 * i) * 256 + ch * 128 + k0);
            #pragma unroll
            for (int kk = 0; kk < 4; kk++) {
                float2 wd[4];
                #pragma unroll
                for (int j = 0; j < 4; j++) {
                    const float w = Ws[(k0 + kk) * 128 + cg + 32 * j];
                    wd[j] = make_float2(w, w);
                }
                #pragma unroll
                for (int t = 0; t < 2; t++) {
                    float2 xp = make_float2(comp4(hq[2 * t], kk), comp4(hq[2 * t + 1], kk));
                    #pragma unroll
                    for (int j = 0; j < 4; j++) ffma2(acc[t][j], xp, wd[j]);
                }
            }
        }
    }

    // residual add, in place
    #pragma unroll
    for (int t = 0; t < 2; t++) {
        const int rA = row0 + rg + 16 * t;
        const int rB = rA + 8;
        #pragma unroll
        for (int j = 0; j < 4; j++) {
            const int c = cg + 32 * j;
            if (rA < R) {
                const size_t ix = (size_t)rA * DD + c;
                Y[ix] = Y[ix] + acc[t][j].x;
            }
            if (rB < R) {
                const size_t ix = (size_t)rB * DD + c;
                Y[ix] = Y[ix] + acc[t][j].y;
            }
        }
    }
}

// ---------------------------------------------------------------------------
extern "C" void kernel_launch(void *const *d_in, const int *in_sizes, int n_in,
                              void *d_out, int out_size)
{
    const float *node   = (const float *)d_in[0];
    const float *edge   = (const float *)d_in[1];
    const int   *src    = (const int *)d_in[2];
    const int   *dst    = (const int *)d_in[3];
    const float *ln1n_w = (const float *)d_in[4];
    const float *ln1n_b = (const float *)d_in[5];
    const float *ln1e_w = (const float *)d_in[6];
    const float *ln1e_b = (const float *)d_in[7];
    const float *ln2n_w = (const float *)d_in[8];
    const float *ln2n_b = (const float *)d_in[9];
    const float *ln2e_w = (const float *)d_in[10];
    const float *ln2e_b = (const float *)d_in[11];
    const float *Wq = (const float *)d_in[12];  const float *bq = (const float *)d_in[13];
    const float *Wk = (const float *)d_in[14];  const float *bk = (const float *)d_in[15];
    const float *Wv = (const float *)d_in[16];  const float *bv = (const float *)d_in[17];
    const float *We = (const float *)d_in[18];  const float *be = (const float *)d_in[19];
    const float *Wo_n = (const float *)d_in[20]; const float *bo_n = (const float *)d_in[21];
    const float *Wo_e = (const float *)d_in[22]; const float *bo_e = (const float *)d_in[23];
    const float *mlp_n_w1 = (const float *)d_in[24];
    const float *mlp_n_w2 = (const float *)d_in[25];
    const float *mlp_e_w1 = (const float *)d_in[26];
    const float *mlp_e_w2 = (const float *)d_in[27];

    float *outh = (float *)d_out;
    float *oute = outh + (size_t)NN * DD;

    float *Qp, *Kp, *Vp, *Pp, *EOp, *wVp, *zp;
    cudaGetSymbolAddress((void **)&Qp,  g_Q);
    cudaGetSymbolAddress((void **)&Kp,  g_K);
    cudaGetSymbolAddress((void **)&Vp,  g_V);
    cudaGetSymbolAddress((void **)&Pp,  g_P);
    cudaGetSymbolAddress((void **)&EOp, g_EO);
    cudaGetSymbolAddress((void **)&wVp, g_wV);
    cudaGetSymbolAddress((void **)&zp,  g_z);

    const int GEMM_SMEM = (64 * 128 + 128 * 128) * 4;               // 96 KB
    const int MLP_SMEM  = (32 * 128 + 32 * 256 + 128 * 128) * 4;    // 112 KB
    cudaFuncSetAttribute(gemm128, cudaFuncAttributeMaxDynamicSharedMemorySize, GEMM_SMEM);
    cudaFuncSetAttribute(mlp128,  cudaFuncAttributeMaxDynamicSharedMemorySize, MLP_SMEM);

    cudaMemsetAsync(wVp, 0, (size_t)NN * DD * sizeof(float), 0);
    cudaMemsetAsync(zp,  0, (size_t)NN * HH * sizeof(float), 0);

    const int GN = (NN + 63) / 64;
    const int GE = (EE + 63) / 64;

    // Q/K/V/E projections with fused LN1
    gemm128<<<GN, 256, GEMM_SMEM>>>(node, ln1n_w, ln1n_b, Wq, bq, nullptr, Qp, NN);
    gemm128<<<GN, 256, GEMM_SMEM>>>(node, ln1n_w, ln1n_b, Wk, bk, nullptr, Kp, NN);
    gemm128<<<GN, 256, GEMM_SMEM>>>(node, ln1n_w, ln1n_b, Wv, bv, nullptr, Vp, NN);
    gemm128<<<GE, 256, GEMM_SMEM>>>(edge, ln1e_w, ln1e_b, We, be, nullptr, Pp, EE);

    // edge attention + scatter
    edge_attn<<<EE / 8, 256>>>(Kp, Qp, Vp, Pp, src, dst, EOp, wVp, zp);
    attn_norm<<<(NN * DD + 255) / 256, 256>>>(wVp, zp);

    // output projections + residual -> d_out
    gemm128<<<GN, 256, GEMM_SMEM>>>(wVp, nullptr, nullptr, Wo_n, bo_n, node, outh, NN);
    gemm128<<<GE, 256, GEMM_SMEM>>>(EOp, nullptr, nullptr, Wo_e, bo_e, edge, oute, EE);

    // LN2 + MLP + residual, in place on d_out
    mlp128<<<(NN + 31) / 32, 256, MLP_SMEM>>>(outh, ln2n_w, ln2n_b, mlp_n_w1, mlp_n_w2, NN);
    mlp128<<<(EE + 31) / 32, 256, MLP_SMEM>>>(oute, ln2e_w, ln2e_b, mlp_e_w1, mlp_e_w2, EE);
}

// round 3
// speedup vs baseline: 1.0648x; 1.0648x over previous
#include <cuda_runtime.h>
#include <cstdint>

#define NN 50000
#define EE 800000
#define DD 128
#define HH 8

// ---------------- scratch (static device arrays; no allocation) ------------
__device__ float g_Q [(size_t)NN * DD];
__device__ float g_K [(size_t)NN * DD];
__device__ float g_V [(size_t)NN * DD];
__device__ float g_P [(size_t)EE * DD];      // proj_e
__device__ float g_EO[(size_t)EE * DD];      // e_out
__device__ float g_wV[(size_t)NN * DD];
__device__ float g_z [(size_t)NN * HH];
__device__ float g_H [(size_t)EE * 2 * DD];  // MLP hidden (silu output)

// =================== tf32 helpers (portable, sm_80+) =======================
__device__ __forceinline__ uint32_t f2tf(float f) {
    uint32_t r;
    asm("cvt.rna.tf32.f32 %0, %1;" : "=r"(r) : "f"(f));
    return r;
}
__device__ __forceinline__ void mma_tf32(float *c, const uint32_t *a,
                                         const uint32_t *b) {
    asm volatile(
        "mma.sync.aligned.m16n8k8.row.col.f32.tf32.tf32.f32 "
        "{%0,%1,%2,%3}, {%4,%5,%6,%7}, {%8,%9}, {%0,%1,%2,%3};"
        : "+f"(c[0]), "+f"(c[1]), "+f"(c[2]), "+f"(c[3])
        : "r"(a[0]), "r"(a[1]), "r"(a[2]), "r"(a[3]), "r"(b[0]), "r"(b[1]));
}

// smem float offsets (floats, not bytes)
#define XS_STRIDE 132
#define F_STAT 0
#define F_X    256
#define F_WH   (F_X + 128 * XS_STRIDE)
#define F_WL   (F_WH + 128 * XS_STRIDE)
#define F_TOT  (F_WL + 128 * XS_STRIDE)     // 50944 floats = 203776 B

// ---------------------------------------------------------------------------
// Tensor-core GEMM (M-tile 128 x N-tile 128), 3xTF32 split via mma.sync:
//   Y[R x No] = epi( LN?(X[R x K]) @ W[K x No] + bias?, silu?, resid? )
// ---------------------------------------------------------------------------
__global__ void __launch_bounds__(256, 1) tcgemm(
    const float *__restrict__ X, int ldx,
    const float *__restrict__ lnw, const float *__restrict__ lnb,
    const float *__restrict__ W, int No,
    const float *__restrict__ bias, const float *__restrict__ resid,
    float *__restrict__ Y, int ldy, int R, int K, int do_silu)
{
    extern __shared__ float sm[];
    float *stat = sm + F_STAT;
    float *Xs   = sm + F_X;
    float *WsH  = sm + F_WH;
    float *WsL  = sm + F_WL;

    const int tid  = threadIdx.x;
    const int wid  = tid >> 5;
    const int lane = tid & 31;
    const int mw   = wid & 3;      // M warp tile (32 rows)
    const int nw   = wid >> 2;     // N warp tile (64 cols)
    const int row0 = blockIdx.x * 128;
    const bool do_ln = (lnw != nullptr);

    // --- LN stats over 128 features ---------------------------------------
    if (do_ln) {
        const int r = tid >> 1;
        const int h = tid & 1;
        float s = 0.f, q = 0.f;
        if (row0 + r < R) {
            const float4 *xr =
                reinterpret_cast<const float4 *>(X + (size_t)(row0 + r) * ldx + h * 64);
            #pragma unroll
            for (int i = 0; i < 16; i++) {
                float4 v = xr[i];
                s += v.x + v.y + v.z + v.w;
                q += v.x * v.x + v.y * v.y + v.z * v.z + v.w * v.w;
            }
        }
        s += __shfl_xor_sync(0xffffffffu, s, 1);
        q += __shfl_xor_sync(0xffffffffu, q, 1);
        const float m = s * (1.f / 128.f);
        stat[r]       = m;
        stat[128 + r] = rsqrtf(q * (1.f / 128.f) - m * m + 1e-5f);
        __syncthreads();
    }

    const int nts    = No >> 7;   // N tiles of 128
    const int chunks = K >> 7;    // K chunks of 128

    for (int nt = 0; nt < nts; nt++) {
        float acc[2][8][4];
        #pragma unroll
        for (int mt = 0; mt < 2; mt++)
            #pragma unroll
            for (int j = 0; j < 8; j++)
                #pragma unroll
                for (int q = 0; q < 4; q++) acc[mt][j][q] = 0.f;

        for (int kc = 0; kc < chunks; kc++) {
            __syncthreads();   // previous chunk's smem reads done

            // ---- load X chunk (with LN) ----------------------------------
            if (nt == 0 || chunks > 1) {
                const int r  = tid >> 1;
                const int ch = (tid & 1) * 64;
                const int grow = row0 + r;
                const bool valid = grow < R;
                float m = 0.f, rs = 0.f;
                if (do_ln) { m = stat[r]; rs = stat[128 + r]; }
                const float4 *xr = reinterpret_cast<const float4 *>(
                    X + (size_t)grow * ldx + kc * 128 + ch);
                float4 *xd = reinterpret_cast<float4 *>(Xs + r * XS_STRIDE + ch);
                #pragma unroll
                for (int i = 0; i < 16; i++) {
                    float4 v = valid ? xr[i] : make_float4(0.f, 0.f, 0.f, 0.f);
                    if (do_ln) {
                        const int gc = ch + 4 * i;
                        v.x = (v.x - m) * rs * lnw[gc + 0] + lnb[gc + 0];
                        v.y = (v.y - m) * rs * lnw[gc + 1] + lnb[gc + 1];
                        v.z = (v.z - m) * rs * lnw[gc + 2] + lnb[gc + 2];
                        v.w = (v.w - m) * rs * lnw[gc + 3] + lnb[gc + 3];
                    }
                    xd[i] = v;
                }
            }

            // ---- load W chunk, pre-split into tf32 hi/lo -----------------
            {
                const int k  = tid >> 1;
                const int nh = (tid & 1) * 64;
                const float4 *wr = reinterpret_cast<const float4 *>(
                    W + (size_t)(kc * 128 + k) * No + nt * 128 + nh);
                float *wh = WsH + k * XS_STRIDE + nh;
                float *wl = WsL + k * XS_STRIDE + nh;
                #pragma unroll
                for (int i = 0; i < 16; i++) {
                    float4 v = wr[i];
                    float4 hv, lv;
                    uint32_t h;
                    h = f2tf(v.x); hv.x = __uint_as_float(h);
                    lv.x = __uint_as_float(f2tf(v.x - hv.x));
                    h = f2tf(v.y); hv.y = __uint_as_float(h);
                    lv.y = __uint_as_float(f2tf(v.y - hv.y));
                    h = f2tf(v.z); hv.z = __uint_as_float(h);
                    lv.z = __uint_as_float(f2tf(v.z - hv.z));
                    h = f2tf(v.w); hv.w = __uint_as_float(h);
                    lv.w = __uint_as_float(f2tf(v.w - hv.w));
                    *reinterpret_cast<float4 *>(wh + 4 * i) = hv;
                    *reinterpret_cast<float4 *>(wl + 4 * i) = lv;
                }
            }
            __syncthreads();

            // ---- MMA over this chunk: 16 k-iters of k8 -------------------
            const int arow = mw * 32 + (lane >> 2);
            const int acol = lane & 3;
            const int bcol = nw * 64 + (lane >> 2);
            const int brow = lane & 3;

            #pragma unroll 4
            for (int kk = 0; kk < 16; kk++) {
                const int k0 = kk * 8;

                // A fragments (2 m16 tiles), split in registers
                uint32_t ah[2][4], al[2][4];
                #pragma unroll
                for (int mt = 0; mt < 2; mt++) {
                    const float *xp = Xs + (arow + mt * 16) * XS_STRIDE + k0 + acol;
                    float r0 = xp[0];
                    float r1 = xp[8 * XS_STRIDE];
                    float r2 = xp[4];
                    float r3 = xp[8 * XS_STRIDE + 4];
                    ah[mt][0] = f2tf(r0);
                    al[mt][0] = f2tf(r0 - __uint_as_float(ah[mt][0]));
                    ah[mt][1] = f2tf(r1);
                    al[mt][1] = f2tf(r1 - __uint_as_float(ah[mt][1]));
                    ah[mt][2] = f2tf(r2);
                    al[mt][2] = f2tf(r2 - __uint_as_float(ah[mt][2]));
                    ah[mt][3] = f2tf(r3);
                    al[mt][3] = f2tf(r3 - __uint_as_float(ah[mt][3]));
                }

                // B fragments from pre-split smem
                uint32_t bh[8][2], bl[8][2];
                #pragma unroll
                for (int j = 0; j < 8; j++) {
                    const int n = bcol + 8 * j;
                    const float *ph = WsH + (k0 + brow) * XS_STRIDE + n;
                    const float *pl = WsL + (k0 + brow) * XS_STRIDE + n;
                    bh[j][0] = __float_as_uint(ph[0]);
                    bh[j][1] = __float_as_uint(ph[4 * XS_STRIDE]);
                    bl[j][0] = __float_as_uint(pl[0]);
                    bl[j][1] = __float_as_uint(pl[4 * XS_STRIDE]);
                }

                // term 1: Ah * Bh
                #pragma unroll
                for (int j = 0; j < 8; j++) {
                    mma_tf32(acc[0][j], ah[0], bh[j]);
                    mma_tf32(acc[1][j], ah[1], bh[j]);
                }
                // term 2: Al * Bh
                #pragma unroll
                for (int j = 0; j < 8; j++) {
                    mma_tf32(acc[0][j], al[0], bh[j]);
                    mma_tf32(acc[1][j], al[1], bh[j]);
                }
                // term 3: Ah * Bl
                #pragma unroll
                for (int j = 0; j < 8; j++) {
                    mma_tf32(acc[0][j], ah[0], bl[j]);
                    mma_tf32(acc[1][j], ah[1], bl[j]);
                }
            }
        }

        // ---- epilogue for this N tile ------------------------------------
        #pragma unroll
        for (int mt = 0; mt < 2; mt++) {
            const int rbase = row0 + mw * 32 + mt * 16 + (lane >> 2);
            #pragma unroll
            for (int half = 0; half < 2; half++) {
                const int r = rbase + half * 8;
                if (r < R) {
                    #pragma unroll
                    for (int j = 0; j < 8; j++) {
                        const int col = nt * 128 + nw * 64 + j * 8 + 2 * (lane & 3);
                        float2 o;
                        o.x = acc[mt][j][half * 2 + 0];
                        o.y = acc[mt][j][half * 2 + 1];
                        if (bias) { o.x += bias[col]; o.y += bias[col + 1]; }
                        if (do_silu) {
                            o.x = o.x / (1.f + __expf(-o.x));
                            o.y = o.y / (1.f + __expf(-o.y));
                        }
                        const size_t yb = (size_t)r * ldy + col;
                        if (resid) { o.x += resid[yb]; o.y += resid[yb + 1]; }
                        *reinterpret_cast<float2 *>(Y + yb) = o;
                    }
                }
            }
        }
    }
}

// ---------------------------------------------------------------------------
// Per-edge attention (R1 version, known-good)
// ---------------------------------------------------------------------------
__global__ void __launch_bounds__(256) edge_attn(
    const float *__restrict__ K, const float *__restrict__ Q,
    const float *__restrict__ V, const float *__restrict__ P,
    const int *__restrict__ src, const int *__restrict__ dst,
    float *__restrict__ eout, float *__restrict__ wV, float *__restrict__ z)
{
    const int e = blockIdx.x * 8 + (threadIdx.x >> 5);
    if (e >= EE) return;
    const int lane = threadIdx.x & 31;
    const int s = src[e];
    const int d = dst[e];

    const float4 kv = reinterpret_cast<const float4 *>(K + (size_t)s * DD)[lane];
    const float4 qv = reinterpret_cast<const float4 *>(Q + (size_t)d * DD)[lane];
    const float4 pv = reinterpret_cast<const float4 *>(P + (size_t)e * DD)[lane];

    float4 eo;
    eo.x = fminf(fmaxf(kv.x * qv.x * 0.25f, -5.f), 5.f) * pv.x;
    eo.y = fminf(fmaxf(kv.y * qv.y * 0.25f, -5.f), 5.f) * pv.y;
    eo.z = fminf(fmaxf(kv.z * qv.z * 0.25f, -5.f), 5.f) * pv.z;
    eo.w = fminf(fmaxf(kv.w * qv.w * 0.25f, -5.f), 5.f) * pv.w;
    reinterpret_cast<float4 *>(eout + (size_t)e * DD)[lane] = eo;

    float ps = eo.x + eo.y + eo.z + eo.w;
    ps += __shfl_xor_sync(0xffffffffu, ps, 1);
    ps += __shfl_xor_sync(0xffffffffu, ps, 2);
    const float w = __expf(fminf(fmaxf(ps, -5.f), 5.f));

    const float4 vv = reinterpret_cast<const float4 *>(V + (size_t)s * DD)[lane];
    float *wvp = wV + (size_t)d * DD + lane * 4;
    atomicAdd(wvp + 0, vv.x * w);
    atomicAdd(wvp + 1, vv.y * w);
    atomicAdd(wvp + 2, vv.z * w);
    atomicAdd(wvp + 3, vv.w * w);
    if ((lane & 3) == 0) atomicAdd(z + (size_t)d * HH + (lane >> 2), w);
}

__global__ void __launch_bounds__(256) attn_norm(float *__restrict__ wV,
                                                 const float *__restrict__ z)
{
    const int i = blockIdx.x * 256 + threadIdx.x;
    if (i < NN * DD) {
        const int n = i >> 7;
        const int c = i & 127;
        wV[i] = wV[i] / (z[(size_t)n * HH + (c >> 4)] + 1e-8f);
    }
}

// ---------------------------------------------------------------------------
extern "C" void kernel_launch(void *const *d_in, const int *in_sizes, int n_in,
                              void *d_out, int out_size)
{
    const float *node   = (const float *)d_in[0];
    const float *edge   = (const float *)d_in[1];
    const int   *src    = (const int *)d_in[2];
    const int   *dst    = (const int *)d_in[3];
    const float *ln1n_w = (const float *)d_in[4];
    const float *ln1n_b = (const float *)d_in[5];
    const float *ln1e_w = (const float *)d_in[6];
    const float *ln1e_b = (const float *)d_in[7];
    const float *ln2n_w = (const float *)d_in[8];
    const float *ln2n_b = (const float *)d_in[9];
    const float *ln2e_w = (const float *)d_in[10];
    const float *ln2e_b = (const float *)d_in[11];
    const float *Wq = (const float *)d_in[12];  const float *bq = (const float *)d_in[13];
    const float *Wk = (const float *)d_in[14];  const float *bk = (const float *)d_in[15];
    const float *Wv = (const float *)d_in[16];  const float *bv = (const float *)d_in[17];
    const float *We = (const float *)d_in[18];  const float *be = (const float *)d_in[19];
    const float *Wo_n = (const float *)d_in[20]; const float *bo_n = (const float *)d_in[21];
    const float *Wo_e = (const float *)d_in[22]; const float *bo_e = (const float *)d_in[23];
    const float *w1n = (const float *)d_in[24];
    const float *w2n = (const float *)d_in[25];
    const float *w1e = (const float *)d_in[26];
    const float *w2e = (const float *)d_in[27];

    float *outh = (float *)d_out;
    float *oute = outh + (size_t)NN * DD;

    float *Qp, *Kp, *Vp, *Pp, *EOp, *wVp, *zp, *Hp;
    cudaGetSymbolAddress((void **)&Qp,  g_Q);
    cudaGetSymbolAddress((void **)&Kp,  g_K);
    cudaGetSymbolAddress((void **)&Vp,  g_V);
    cudaGetSymbolAddress((void **)&Pp,  g_P);
    cudaGetSymbolAddress((void **)&EOp, g_EO);
    cudaGetSymbolAddress((void **)&wVp, g_wV);
    cudaGetSymbolAddress((void **)&zp,  g_z);
    cudaGetSymbolAddress((void **)&Hp,  g_H);

    const int SMEM = F_TOT * 4;   // 203776 bytes
    cudaFuncSetAttribute(tcgemm, cudaFuncAttributeMaxDynamicSharedMemorySize, SMEM);

    cudaMemsetAsync(wVp, 0, (size_t)NN * DD * sizeof(float), 0);
    cudaMemsetAsync(zp,  0, (size_t)NN * HH * sizeof(float), 0);

    auto T = [&](const float *X, int ldx, const float *lw, const float *lb,
                 const float *W, int No, const float *bias, const float *resid,
                 float *Y, int ldy, int R, int K, int silu) {
        tcgemm<<<(R + 127) / 128, 256, SMEM>>>(X, ldx, lw, lb, W, No, bias,
                                               resid, Y, ldy, R, K, silu);
    };

    // LN1 + Q/K/V/E projections
    T(node, 128, ln1n_w, ln1n_b, Wq, 128, bq, nullptr, Qp, 128, NN, 128, 0);
    T(node, 128, ln1n_w, ln1n_b, Wk, 128, bk, nullptr, Kp, 128, NN, 128, 0);
    T(node, 128, ln1n_w, ln1n_b, Wv, 128, bv, nullptr, Vp, 128, NN, 128, 0);
    T(edge, 128, ln1e_w, ln1e_b, We, 128, be, nullptr, Pp, 128, EE, 128, 0);

    // edge attention + scatter + normalize
    edge_attn<<<EE / 8, 256>>>(Kp, Qp, Vp, Pp, src, dst, EOp, wVp, zp);
    attn_norm<<<(NN * DD + 255) / 256, 256>>>(wVp, zp);

    // output projections + residual -> d_out
    T(wVp, 128, nullptr, nullptr, Wo_n, 128, bo_n, node, outh, 128, NN, 128, 0);
    T(EOp, 128, nullptr, nullptr, Wo_e, 128, bo_e, edge, oute, 128, EE, 128, 0);

    // node MLP: LN2 + silu(x@W1) -> H ; H@W2 + resid -> outh (in place)
    T(outh, 128, ln2n_w, ln2n_b, w1n, 256, nullptr, nullptr, Hp, 256, NN, 128, 1);
    T(Hp, 256, nullptr, nullptr, w2n, 128, nullptr, outh, outh, 128, NN, 256, 0);

    // edge MLP
    T(oute, 128, ln2e_w, ln2e_b, w1e, 256, nullptr, nullptr, Hp, 256, EE, 128, 1);
    T(Hp, 256, nullptr, nullptr, w2e, 128, nullptr, oute, oute, 128, EE, 256, 0);
}

// round 4
// speedup vs baseline: 1.7736x; 1.6657x over previous
#include <cuda_runtime.h>
#include <cuda_bf16.h>
#include <cstdint>

#define NN 50000
#define EE 800000
#define DD 128
#define HH 8

// ---------------- scratch (static device arrays; no allocation) ------------
__device__ float g_QKV[(size_t)NN * 384];
__device__ float g_P [(size_t)EE * DD];      // proj_e
__device__ float g_EO[(size_t)EE * DD];      // e_out
__device__ float g_wV[(size_t)NN * DD];
__device__ float g_z [(size_t)NN * HH];
__device__ float g_H [(size_t)EE * 2 * DD];  // MLP hidden
__device__ float g_bqkv[384];

// pre-split weights: bf16 hi/lo, [n][k] layout, packed in one buffer
// offsets (elements):
#define OF_QKV  0                      // 384 x 128
#define OF_WE   49152                  // 128 x 128
#define OF_WON  65536
#define OF_WOE  81920
#define OF_W1N  98304                  // 256 x 128
#define OF_W2N  131072                 // 128 x 256
#define OF_W1E  163840
#define OF_W2E  196608
#define W_TOT   229376
__device__ __nv_bfloat16 g_WH[W_TOT];
__device__ __nv_bfloat16 g_WL[W_TOT];

// =================== helpers ===============================================
__device__ __forceinline__ void mma_bf16(float *c, const uint32_t *a,
                                         const uint32_t *b) {
    asm volatile(
        "mma.sync.aligned.m16n8k16.row.col.f32.bf16.bf16.f32 "
        "{%0,%1,%2,%3}, {%4,%5,%6,%7}, {%8,%9}, {%0,%1,%2,%3};"
        : "+f"(c[0]), "+f"(c[1]), "+f"(c[2]), "+f"(c[3])
        : "r"(a[0]), "r"(a[1]), "r"(a[2]), "r"(a[3]), "r"(b[0]), "r"(b[1]));
}
__device__ __forceinline__ uint32_t pack_bf2(float x, float y) {
    __nv_bfloat162 t = __floats2bfloat162_rn(x, y);
    return *reinterpret_cast<uint32_t *>(&t);
}
__device__ __forceinline__ void split2(float x, float y, uint32_t &h, uint32_t &l) {
    __nv_bfloat16 hx = __float2bfloat16(x);
    __nv_bfloat16 hy = __float2bfloat16(y);
    float lx = x - __bfloat162float(hx);
    float ly = y - __bfloat162float(hy);
    __nv_bfloat162 hp; hp.x = hx; hp.y = hy;
    h = *reinterpret_cast<uint32_t *>(&hp);
    l = pack_bf2(lx, ly);
}

// smem: bf16 arrays, stride 136 bf16 per row
#define SSTR 136
#define S_AH 0
#define S_AL (128 * SSTR * 2)          // 34816 B
#define S_BH (S_AL + 128 * SSTR * 2)   // 69632
#define S_BL (S_BH + 128 * SSTR * 2)   // 104448
#define S_TOT (S_BL + 128 * SSTR * 2)  // 139264 B

// ---------------------------------------------------------------------------
// BF16x3 tensor-core GEMM, M-tile 128, N-tile 128, 512 threads (16 warps,
// 4x4 grid of 32x32 warp tiles).
//   Y[R x No] = epi( LN?(X[R x K]) @ W[K x No] + bias?, silu?, resid? )
// WH/WL: pre-split weights in [n][k] bf16 layout.
// ---------------------------------------------------------------------------
__global__ void __launch_bounds__(512, 1) tcgemm(
    const float *__restrict__ X, int ldx,
    const float *__restrict__ lnw, const float *__restrict__ lnb,
    const __nv_bfloat16 *__restrict__ WH, const __nv_bfloat16 *__restrict__ WL,
    int No, const float *__restrict__ bias, const float *__restrict__ resid,
    float *__restrict__ Y, int ldy, int R, int K, int do_silu)
{
    extern __shared__ char smc[];
    uint32_t *AHu = reinterpret_cast<uint32_t *>(smc + S_AH);
    uint32_t *ALu = reinterpret_cast<uint32_t *>(smc + S_AL);
    uint32_t *BHu = reinterpret_cast<uint32_t *>(smc + S_BH);
    uint32_t *BLu = reinterpret_cast<uint32_t *>(smc + S_BL);

    const int tid  = threadIdx.x;
    const int wid  = tid >> 5;
    const int lane = tid & 31;
    const int mw   = wid & 3;
    const int nw   = wid >> 2;
    const int row0 = blockIdx.x * 128;
    const bool do_ln = (lnw != nullptr);

    const int nts    = No >> 7;
    const int chunks = K >> 7;

    for (int nt = 0; nt < nts; nt++) {
        float acc[2][4][4];
        #pragma unroll
        for (int mt = 0; mt < 2; mt++)
            #pragma unroll
            for (int j = 0; j < 4; j++)
                #pragma unroll
                for (int q = 0; q < 4; q++) acc[mt][j][q] = 0.f;

        for (int kc = 0; kc < chunks; kc++) {
            __syncthreads();

            // ---- A: load X chunk rows, LN in-register, split to bf16 -----
            if (nt == 0 || chunks > 1) {
                const int r  = tid >> 2;          // 0..127
                const int c0 = (tid & 3) * 32;
                const bool valid = (row0 + r) < R;
                float4 v[8];
                if (valid) {
                    const float4 *xr = reinterpret_cast<const float4 *>(
                        X + (size_t)(row0 + r) * ldx + kc * 128 + c0);
                    #pragma unroll
                    for (int i = 0; i < 8; i++) v[i] = xr[i];
                } else {
                    #pragma unroll
                    for (int i = 0; i < 8; i++) v[i] = make_float4(0.f, 0.f, 0.f, 0.f);
                }
                if (do_ln) {
                    float s = 0.f, q = 0.f;
                    #pragma unroll
                    for (int i = 0; i < 8; i++) {
                        s += v[i].x + v[i].y + v[i].z + v[i].w;
                        q += v[i].x * v[i].x + v[i].y * v[i].y +
                             v[i].z * v[i].z + v[i].w * v[i].w;
                    }
                    s += __shfl_xor_sync(0xffffffffu, s, 1);
                    s += __shfl_xor_sync(0xffffffffu, s, 2);
                    q += __shfl_xor_sync(0xffffffffu, q, 1);
                    q += __shfl_xor_sync(0xffffffffu, q, 2);
                    const float m  = s * (1.f / 128.f);
                    const float rs = rsqrtf(q * (1.f / 128.f) - m * m + 1e-5f);
                    #pragma unroll
                    for (int i = 0; i < 8; i++) {
                        const int gc = c0 + 4 * i;
                        v[i].x = (v[i].x - m) * rs * lnw[gc + 0] + lnb[gc + 0];
                        v[i].y = (v[i].y - m) * rs * lnw[gc + 1] + lnb[gc + 1];
                        v[i].z = (v[i].z - m) * rs * lnw[gc + 2] + lnb[gc + 2];
                        v[i].w = (v[i].w - m) * rs * lnw[gc + 3] + lnb[gc + 3];
                    }
                }
                #pragma unroll
                for (int i = 0; i < 8; i++) {
                    const int idx = (r * SSTR + c0 + 4 * i) >> 1;  // u32 index
                    uint32_t h0, l0, h1, l1;
                    split2(v[i].x, v[i].y, h0, l0);
                    split2(v[i].z, v[i].w, h1, l1);
                    AHu[idx] = h0; AHu[idx + 1] = h1;
                    ALu[idx] = l0; ALu[idx + 1] = l1;
                }
            }

            // ---- B: coalesced copy of pre-split W^T chunk ----------------
            {
                const int n  = tid >> 2;          // 0..127
                const int k0 = (tid & 3) * 32;
                const size_t gofs = (size_t)(nt * 128 + n) * K + kc * 128 + k0;
                const uint4 *sh = reinterpret_cast<const uint4 *>(WH + gofs);
                const uint4 *sl = reinterpret_cast<const uint4 *>(WL + gofs);
                uint4 *dh = reinterpret_cast<uint4 *>(
                    reinterpret_cast<char *>(BHu) + (n * SSTR + k0) * 2);
                uint4 *dl = reinterpret_cast<uint4 *>(
                    reinterpret_cast<char *>(BLu) + (n * SSTR + k0) * 2);
                #pragma unroll
                for (int i = 0; i < 4; i++) { dh[i] = sh[i]; dl[i] = sl[i]; }
            }
            __syncthreads();

            // ---- MMA: 8 k16-iters ----------------------------------------
            const int arow = mw * 32 + (lane >> 2);
            const int ac   = 2 * (lane & 3);

            #pragma unroll 2
            for (int kk = 0; kk < 8; kk++) {
                const int k0 = kk * 16;
                uint32_t ah[2][4], al[2][4];
                #pragma unroll
                for (int mt = 0; mt < 2; mt++) {
                    const int b = ((arow + 16 * mt) * SSTR + k0 + ac) >> 1;
                    ah[mt][0] = AHu[b];
                    ah[mt][1] = AHu[b + 4 * SSTR];
                    ah[mt][2] = AHu[b + 4];
                    ah[mt][3] = AHu[b + 4 * SSTR + 4];
                    al[mt][0] = ALu[b];
                    al[mt][1] = ALu[b + 4 * SSTR];
                    al[mt][2] = ALu[b + 4];
                    al[mt][3] = ALu[b + 4 * SSTR + 4];
                }
                uint32_t bh[4][2], bl[4][2];
                #pragma unroll
                for (int j = 0; j < 4; j++) {
                    const int n = nw * 32 + j * 8 + (lane >> 2);
                    const int b = (n * SSTR + k0 + ac) >> 1;
                    bh[j][0] = BHu[b];
                    bh[j][1] = BHu[b + 4];
                    bl[j][0] = BLu[b];
                    bl[j][1] = BLu[b + 4];
                }
                #pragma unroll
                for (int j = 0; j < 4; j++) {
                    mma_bf16(acc[0][j], ah[0], bh[j]);
                    mma_bf16(acc[1][j], ah[1], bh[j]);
                }
                #pragma unroll
                for (int j = 0; j < 4; j++) {
                    mma_bf16(acc[0][j], al[0], bh[j]);
                    mma_bf16(acc[1][j], al[1], bh[j]);
                }
                #pragma unroll
                for (int j = 0; j < 4; j++) {
                    mma_bf16(acc[0][j], ah[0], bl[j]);
                    mma_bf16(acc[1][j], ah[1], bl[j]);
                }
            }
        }

        // ---- epilogue --------------------------------------------------
        #pragma unroll
        for (int mt = 0; mt < 2; mt++) {
            #pragma unroll
            for (int half = 0; half < 2; half++) {
                const int r = row0 + mw * 32 + mt * 16 + (lane >> 2) + half * 8;
                if (r < R) {
                    #pragma unroll
                    for (int j = 0; j < 4; j++) {
                        const int col = nt * 128 + nw * 32 + j * 8 + 2 * (lane & 3);
                        float2 o;
                        o.x = acc[mt][j][half * 2 + 0];
                        o.y = acc[mt][j][half * 2 + 1];
                        if (bias) { o.x += bias[col]; o.y += bias[col + 1]; }
                        if (do_silu) {
                            o.x = o.x / (1.f + __expf(-o.x));
                            o.y = o.y / (1.f + __expf(-o.y));
                        }
                        const size_t yb = (size_t)r * ldy + col;
                        if (resid) { o.x += resid[yb]; o.y += resid[yb + 1]; }
                        *reinterpret_cast<float2 *>(Y + yb) = o;
                    }
                }
            }
        }
    }
}

// ---------------------------------------------------------------------------
// weight pre-split: W[K][No] fp32 -> H/L [n][k] bf16
// ---------------------------------------------------------------------------
__global__ void split_w(const float *__restrict__ W,
                        __nv_bfloat16 *__restrict__ H,
                        __nv_bfloat16 *__restrict__ L, int K, int No)
{
    const int i = blockIdx.x * 256 + threadIdx.x;
    if (i < K * No) {
        const int k = i / No;
        const int n = i - k * No;
        const float v = W[i];
        const __nv_bfloat16 h = __float2bfloat16(v);
        H[(size_t)n * K + k] = h;
        L[(size_t)n * K + k] = __float2bfloat16(v - __bfloat162float(h));
    }
}

__global__ void pack_bias(const float *__restrict__ a, const float *__restrict__ b,
                          const float *__restrict__ c, float *__restrict__ o)
{
    const int i = threadIdx.x;
    if (i < 128) { o[i] = a[i]; o[128 + i] = b[i]; o[256 + i] = c[i]; }
}

// ---------------------------------------------------------------------------
// Per-edge attention (QKV packed rows of 384: [Q|K|V])
// ---------------------------------------------------------------------------
__global__ void __launch_bounds__(256) edge_attn(
    const float *__restrict__ QKV, const float *__restrict__ P,
    const int *__restrict__ src, const int *__restrict__ dst,
    float *__restrict__ eout, float *__restrict__ wV, float *__restrict__ z)
{
    const int e = blockIdx.x * 8 + (threadIdx.x >> 5);
    if (e >= EE) return;
    const int lane = threadIdx.x & 31;
    const int s = src[e];
    const int d = dst[e];

    const float4 kv = reinterpret_cast<const float4 *>(QKV + (size_t)s * 384 + 128)[lane];
    const float4 qv = reinterpret_cast<const float4 *>(QKV + (size_t)d * 384)[lane];
    const float4 pv = reinterpret_cast<const float4 *>(P + (size_t)e * DD)[lane];

    float4 eo;
    eo.x = fminf(fmaxf(kv.x * qv.x * 0.25f, -5.f), 5.f) * pv.x;
    eo.y = fminf(fmaxf(kv.y * qv.y * 0.25f, -5.f), 5.f) * pv.y;
    eo.z = fminf(fmaxf(kv.z * qv.z * 0.25f, -5.f), 5.f) * pv.z;
    eo.w = fminf(fmaxf(kv.w * qv.w * 0.25f, -5.f), 5.f) * pv.w;
    reinterpret_cast<float4 *>(eout + (size_t)e * DD)[lane] = eo;

    float ps = eo.x + eo.y + eo.z + eo.w;
    ps += __shfl_xor_sync(0xffffffffu, ps, 1);
    ps += __shfl_xor_sync(0xffffffffu, ps, 2);
    const float w = __expf(fminf(fmaxf(ps, -5.f), 5.f));

    const float4 vv = reinterpret_cast<const float4 *>(QKV + (size_t)s * 384 + 256)[lane];
    float *wvp = wV + (size_t)d * DD + lane * 4;
    atomicAdd(wvp + 0, vv.x * w);
    atomicAdd(wvp + 1, vv.y * w);
    atomicAdd(wvp + 2, vv.z * w);
    atomicAdd(wvp + 3, vv.w * w);
    if ((lane & 3) == 0) atomicAdd(z + (size_t)d * HH + (lane >> 2), w);
}

__global__ void __launch_bounds__(256) attn_norm(float *__restrict__ wV,
                                                 const float *__restrict__ z)
{
    const int i = blockIdx.x * 256 + threadIdx.x;
    if (i < NN * DD) {
        const int n = i >> 7;
        const int c = i & 127;
        wV[i] = wV[i] / (z[(size_t)n * HH + (c >> 4)] + 1e-8f);
    }
}

// ---------------------------------------------------------------------------
extern "C" void kernel_launch(void *const *d_in, const int *in_sizes, int n_in,
                              void *d_out, int out_size)
{
    const float *node   = (const float *)d_in[0];
    const float *edge   = (const float *)d_in[1];
    const int   *src    = (const int *)d_in[2];
    const int   *dst    = (const int *)d_in[3];
    const float *ln1n_w = (const float *)d_in[4];
    const float *ln1n_b = (const float *)d_in[5];
    const float *ln1e_w = (const float *)d_in[6];
    const float *ln1e_b = (const float *)d_in[7];
    const float *ln2n_w = (const float *)d_in[8];
    const float *ln2n_b = (const float *)d_in[9];
    const float *ln2e_w = (const float *)d_in[10];
    const float *ln2e_b = (const float *)d_in[11];
    const float *Wq = (const float *)d_in[12];  const float *bq = (const float *)d_in[13];
    const float *Wk = (const float *)d_in[14];  const float *bk = (const float *)d_in[15];
    const float *Wv = (const float *)d_in[16];  const float *bv = (const float *)d_in[17];
    const float *We = (const float *)d_in[18];  const float *be = (const float *)d_in[19];
    const float *Wo_n = (const float *)d_in[20]; const float *bo_n = (const float *)d_in[21];
    const float *Wo_e = (const float *)d_in[22]; const float *bo_e = (const float *)d_in[23];
    const float *w1n = (const float *)d_in[24];
    const float *w2n = (const float *)d_in[25];
    const float *w1e = (const float *)d_in[26];
    const float *w2e = (const float *)d_in[27];

    float *outh = (float *)d_out;
    float *oute = outh + (size_t)NN * DD;

    float *QKVp, *Pp, *EOp, *wVp, *zp, *Hp, *bqkv;
    __nv_bfloat16 *WHp, *WLp;
    cudaGetSymbolAddress((void **)&QKVp, g_QKV);
    cudaGetSymbolAddress((void **)&Pp,  g_P);
    cudaGetSymbolAddress((void **)&EOp, g_EO);
    cudaGetSymbolAddress((void **)&wVp, g_wV);
    cudaGetSymbolAddress((void **)&zp,  g_z);
    cudaGetSymbolAddress((void **)&Hp,  g_H);
    cudaGetSymbolAddress((void **)&bqkv, g_bqkv);
    cudaGetSymbolAddress((void **)&WHp, g_WH);
    cudaGetSymbolAddress((void **)&WLp, g_WL);

    cudaFuncSetAttribute(tcgemm, cudaFuncAttributeMaxDynamicSharedMemorySize, S_TOT);

    // weight pre-split (tiny)
    auto SW = [&](const float *W, int ofs, int K, int No) {
        split_w<<<(K * No + 255) / 256, 256>>>(W, WHp + ofs, WLp + ofs, K, No);
    };
    SW(Wq, OF_QKV, 128, 128);
    SW(Wk, OF_QKV + 128 * 128, 128, 128);
    SW(Wv, OF_QKV + 256 * 128, 128, 128);
    SW(We, OF_WE, 128, 128);
    SW(Wo_n, OF_WON, 128, 128);
    SW(Wo_e, OF_WOE, 128, 128);
    SW(w1n, OF_W1N, 128, 256);
    SW(w2n, OF_W2N, 256, 128);
    SW(w1e, OF_W1E, 128, 256);
    SW(w2e, OF_W2E, 256, 128);
    pack_bias<<<1, 128>>>(bq, bk, bv, bqkv);

    cudaMemsetAsync(wVp, 0, (size_t)NN * DD * sizeof(float), 0);
    cudaMemsetAsync(zp,  0, (size_t)NN * HH * sizeof(float), 0);

    auto T = [&](const float *X, int ldx, const float *lw, const float *lb,
                 int wofs, int No, const float *bias, const float *resid,
                 float *Y, int ldy, int R, int K, int silu) {
        tcgemm<<<(R + 127) / 128, 512, S_TOT>>>(X, ldx, lw, lb, WHp + wofs,
                                                WLp + wofs, No, bias, resid,
                                                Y, ldy, R, K, silu);
    };

    // LN1 + fused QKV projection (No=384) ; edge projection
    T(node, 128, ln1n_w, ln1n_b, OF_QKV, 384, bqkv, nullptr, QKVp, 384, NN, 128, 0);
    T(edge, 128, ln1e_w, ln1e_b, OF_WE, 128, be, nullptr, Pp, 128, EE, 128, 0);

    // edge attention + scatter + normalize
    edge_attn<<<EE / 8, 256>>>(QKVp, Pp, src, dst, EOp, wVp, zp);
    attn_norm<<<(NN * DD + 255) / 256, 256>>>(wVp, zp);

    // output projections + residual -> d_out
    T(wVp, 128, nullptr, nullptr, OF_WON, 128, bo_n, node, outh, 128, NN, 128, 0);
    T(EOp, 128, nullptr, nullptr, OF_WOE, 128, bo_e, edge, oute, 128, EE, 128, 0);

    // node MLP: LN2 + silu(x@W1) -> H ; H@W2 + resid -> outh (in place)
    T(outh, 128, ln2n_w, ln2n_b, OF_W1N, 256, nullptr, nullptr, Hp, 256, NN, 128, 1);
    T(Hp, 256, nullptr, nullptr, OF_W2N, 128, nullptr, outh, outh, 128, NN, 256, 0);

    // edge MLP
    T(oute, 128, ln2e_w, ln2e_b, OF_W1E, 256, nullptr, nullptr, Hp, 256, EE, 128, 1);
    T(Hp, 256, nullptr, nullptr, OF_W2E, 128, nullptr, oute, oute, 128, EE, 256, 0);
}

// round 5
// speedup vs baseline: 1.8753x; 1.0573x over previous
#include <cuda_runtime.h>
#include <cuda_bf16.h>
#include <cstdint>

#define NN 50000
#define EE 800000
#define DD 128
#define HH 8

// ---------------- scratch (static device arrays; no allocation) ------------
__device__ float g_QKV[(size_t)NN * 384];
__device__ float g_P [(size_t)EE * DD];      // proj_e
__device__ float g_wV[(size_t)NN * DD];
__device__ float g_z [(size_t)NN * HH];
__device__ float g_bqkv[384];

// pre-split weights: bf16 hi/lo, [n][k] layout, packed in one buffer
#define OF_QKV  0                      // 384 x 128
#define OF_WE   49152                  // 128 x 128
#define OF_WON  65536
#define OF_WOE  81920
#define OF_W1N  98304                  // 256 x 128
#define OF_W2N  131072                 // 128 x 256
#define OF_W1E  163840
#define OF_W2E  196608
#define W_TOT   229376
__device__ __nv_bfloat16 g_WH[W_TOT];
__device__ __nv_bfloat16 g_WL[W_TOT];

// =================== helpers ===============================================
__device__ __forceinline__ void mma_bf16(float *c, const uint32_t *a,
                                         const uint32_t *b) {
    asm volatile(
        "mma.sync.aligned.m16n8k16.row.col.f32.bf16.bf16.f32 "
        "{%0,%1,%2,%3}, {%4,%5,%6,%7}, {%8,%9}, {%0,%1,%2,%3};"
        : "+f"(c[0]), "+f"(c[1]), "+f"(c[2]), "+f"(c[3])
        : "r"(a[0]), "r"(a[1]), "r"(a[2]), "r"(a[3]), "r"(b[0]), "r"(b[1]));
}
__device__ __forceinline__ uint32_t pack_bf2(float x, float y) {
    __nv_bfloat162 t = __floats2bfloat162_rn(x, y);
    return *reinterpret_cast<uint32_t *>(&t);
}
__device__ __forceinline__ void split2(float x, float y, uint32_t &h, uint32_t &l) {
    __nv_bfloat16 hx = __float2bfloat16(x);
    __nv_bfloat16 hy = __float2bfloat16(y);
    float lx = x - __bfloat162float(hx);
    float ly = y - __bfloat162float(hy);
    __nv_bfloat162 hp; hp.x = hx; hp.y = hy;
    h = *reinterpret_cast<uint32_t *>(&hp);
    l = pack_bf2(lx, ly);
}
__device__ __forceinline__ void cp16(uint32_t saddr, const void *g) {
    asm volatile("cp.async.cg.shared.global [%0], [%1], 16;"
                 :: "r"(saddr), "l"(g));
}
#define CP_COMMIT() asm volatile("cp.async.commit_group;" ::: "memory")
#define CP_WAIT(n)  asm volatile("cp.async.wait_group %0;" :: "n"(n) : "memory")
#define CLIP5(x) fminf(fmaxf((x), -5.f), 5.f)

// A-style smem stride (bf16), W-buffer stride (bf16, for 64-k tiles)
#define SSTR 136
#define WSTR 72

// one 128x128(A) x [128n x 64k](B) MMA pass, 3-term bf16 split
__device__ __forceinline__ void mma_tile(
    float acc[2][4][4],
    const uint32_t *AH, const uint32_t *AL, int kbase,
    const uint32_t *BH, const uint32_t *BL,
    int mw, int nw, int lane)
{
    const int arow = mw * 32 + (lane >> 2);
    #pragma unroll
    for (int kk = 0; kk < 4; kk++) {
        const int kA = kbase + kk * 16;
        const int kB = kk * 16;
        uint32_t ah[2][4], al[2][4];
        #pragma unroll
        for (int mt = 0; mt < 2; mt++) {
            const int b = (((arow + 16 * mt) * SSTR + kA) >> 1) + (lane & 3);
            ah[mt][0] = AH[b];
            ah[mt][1] = AH[b + 4 * SSTR];
            ah[mt][2] = AH[b + 4];
            ah[mt][3] = AH[b + 4 * SSTR + 4];
            al[mt][0] = AL[b];
            al[mt][1] = AL[b + 4 * SSTR];
            al[mt][2] = AL[b + 4];
            al[mt][3] = AL[b + 4 * SSTR + 4];
        }
        uint32_t bh[4][2], bl[4][2];
        #pragma unroll
        for (int j = 0; j < 4; j++) {
            const int n = nw * 32 + j * 8 + (lane >> 2);
            const int b = ((n * WSTR + kB) >> 1) + (lane & 3);
            bh[j][0] = BH[b];
            bh[j][1] = BH[b + 4];
            bl[j][0] = BL[b];
            bl[j][1] = BL[b + 4];
        }
        #pragma unroll
        for (int j = 0; j < 4; j++) {
            mma_bf16(acc[0][j], ah[0], bh[j]);
            mma_bf16(acc[1][j], ah[1], bh[j]);
        }
        #pragma unroll
        for (int j = 0; j < 4; j++) {
            mma_bf16(acc[0][j], al[0], bh[j]);
            mma_bf16(acc[1][j], al[1], bh[j]);
        }
        #pragma unroll
        for (int j = 0; j < 4; j++) {
            mma_bf16(acc[0][j], ah[0], bl[j]);
            mma_bf16(acc[1][j], ah[1], bl[j]);
        }
    }
}

// cp.async load of a [128n x 64k] hi/lo W tile into a WSTR-strided buffer
__device__ __forceinline__ void loadW(
    char *smem_hi, char *smem_lo,
    const __nv_bfloat16 *WH, const __nv_bfloat16 *WL,
    int Kw, int nrow_base, int kofs, int tid)
{
    const int n = tid >> 2;
    const int q = (tid & 3) * 16;
    const size_t g = (size_t)(nrow_base + n) * Kw + kofs + q;
    const uint32_t dh = (uint32_t)__cvta_generic_to_shared(
        smem_hi + (n * WSTR + q) * 2);
    const uint32_t dl = (uint32_t)__cvta_generic_to_shared(
        smem_lo + (n * WSTR + q) * 2);
    cp16(dh, WH + g);
    cp16(dh + 16, WH + g + 8);
    cp16(dl, WL + g);
    cp16(dl + 16, WL + g + 8);
}

// ======================= generic plain GEMM ================================
// smem layout for tcgemm (B stride = SSTR, full 128k tiles):
#define G_AH 0
#define G_AL 34816
#define G_BH 69632
#define G_BL 104448
#define G_TOT 139264

__global__ void __launch_bounds__(512, 1) tcgemm(
    const float *__restrict__ X, int ldx,
    const float *__restrict__ lnw, const float *__restrict__ lnb,
    const float *__restrict__ zdiv,
    const __nv_bfloat16 *__restrict__ WH, const __nv_bfloat16 *__restrict__ WL,
    int No, const float *__restrict__ bias, const float *__restrict__ resid,
    float *__restrict__ Y, int ldy, int R)
{
    extern __shared__ char smc[];
    uint32_t *AHu = reinterpret_cast<uint32_t *>(smc + G_AH);
    uint32_t *ALu = reinterpret_cast<uint32_t *>(smc + G_AL);
    uint32_t *BHu = reinterpret_cast<uint32_t *>(smc + G_BH);
    uint32_t *BLu = reinterpret_cast<uint32_t *>(smc + G_BL);

    const int tid  = threadIdx.x;
    const int wid  = tid >> 5;
    const int lane = tid & 31;
    const int mw   = wid & 3;
    const int nw   = wid >> 2;
    const int row0 = blockIdx.x * 128;
    const bool do_ln = (lnw != nullptr);
    const int nts = No >> 7;

    // ---- A: load rows, optional LN / z-normalize, split to bf16 ----------
    {
        const int r  = tid >> 2;
        const int c0 = (tid & 3) * 32;
        const int grow = row0 + r;
        const bool valid = grow < R;
        float4 v[8];
        if (valid) {
            const float4 *xr = reinterpret_cast<const float4 *>(
                X + (size_t)grow * ldx + c0);
            #pragma unroll
            for (int i = 0; i < 8; i++) v[i] = xr[i];
        } else {
            #pragma unroll
            for (int i = 0; i < 8; i++) v[i] = make_float4(0.f, 0.f, 0.f, 0.f);
        }
        if (zdiv && valid) {
            const float rA = 1.f / (zdiv[(size_t)grow * 8 + (c0 >> 4)] + 1e-8f);
            const float rB = 1.f / (zdiv[(size_t)grow * 8 + (c0 >> 4) + 1] + 1e-8f);
            #pragma unroll
            for (int i = 0; i < 8; i++) {
                const float s = (i < 4) ? rA : rB;
                v[i].x *= s; v[i].y *= s; v[i].z *= s; v[i].w *= s;
            }
        }
        if (do_ln) {
            float s = 0.f, q = 0.f;
            #pragma unroll
            for (int i = 0; i < 8; i++) {
                s += v[i].x + v[i].y + v[i].z + v[i].w;
                q += v[i].x * v[i].x + v[i].y * v[i].y +
                     v[i].z * v[i].z + v[i].w * v[i].w;
            }
            s += __shfl_xor_sync(0xffffffffu, s, 1);
            s += __shfl_xor_sync(0xffffffffu, s, 2);
            q += __shfl_xor_sync(0xffffffffu, q, 1);
            q += __shfl_xor_sync(0xffffffffu, q, 2);
            const float m  = s * (1.f / 128.f);
            const float rs = rsqrtf(q * (1.f / 128.f) - m * m + 1e-5f);
            #pragma unroll
            for (int i = 0; i < 8; i++) {
                const int gc = c0 + 4 * i;
                v[i].x = (v[i].x - m) * rs * lnw[gc + 0] + lnb[gc + 0];
                v[i].y = (v[i].y - m) * rs * lnw[gc + 1] + lnb[gc + 1];
                v[i].z = (v[i].z - m) * rs * lnw[gc + 2] + lnb[gc + 2];
                v[i].w = (v[i].w - m) * rs * lnw[gc + 3] + lnb[gc + 3];
            }
        }
        #pragma unroll
        for (int i = 0; i < 8; i++) {
            const int idx = (r * SSTR + c0 + 4 * i) >> 1;
            uint32_t h0, l0, h1, l1;
            split2(v[i].x, v[i].y, h0, l0);
            split2(v[i].z, v[i].w, h1, l1);
            AHu[idx] = h0; AHu[idx + 1] = h1;
            ALu[idx] = l0; ALu[idx + 1] = l1;
        }
    }

    for (int nt = 0; nt < nts; nt++) {
        __syncthreads();
        // B: coalesced copy of pre-split W^T tile [128n][128k]
        {
            const int n  = tid >> 2;
            const int k0 = (tid & 3) * 32;
            const size_t gofs = (size_t)(nt * 128 + n) * 128 + k0;
            const uint4 *sh = reinterpret_cast<const uint4 *>(WH + gofs);
            const uint4 *sl = reinterpret_cast<const uint4 *>(WL + gofs);
            uint4 *dh = reinterpret_cast<uint4 *>(
                reinterpret_cast<char *>(BHu) + (n * SSTR + k0) * 2);
            uint4 *dl = reinterpret_cast<uint4 *>(
                reinterpret_cast<char *>(BLu) + (n * SSTR + k0) * 2);
            #pragma unroll
            for (int i = 0; i < 4; i++) { dh[i] = sh[i]; dl[i] = sl[i]; }
        }
        __syncthreads();

        float acc[2][4][4];
        #pragma unroll
        for (int mt = 0; mt < 2; mt++)
            #pragma unroll
            for (int j = 0; j < 4; j++)
                #pragma unroll
                for (int q = 0; q < 4; q++) acc[mt][j][q] = 0.f;

        // MMA: 8 k16-iters (B stride SSTR here)
        const int arow = mw * 32 + (lane >> 2);
        #pragma unroll 2
        for (int kk = 0; kk < 8; kk++) {
            const int k0 = kk * 16;
            uint32_t ah[2][4], al[2][4];
            #pragma unroll
            for (int mt = 0; mt < 2; mt++) {
                const int b = (((arow + 16 * mt) * SSTR + k0) >> 1) + (lane & 3);
                ah[mt][0] = AHu[b];
                ah[mt][1] = AHu[b + 4 * SSTR];
                ah[mt][2] = AHu[b + 4];
                ah[mt][3] = AHu[b + 4 * SSTR + 4];
                al[mt][0] = ALu[b];
                al[mt][1] = ALu[b + 4 * SSTR];
                al[mt][2] = ALu[b + 4];
                al[mt][3] = ALu[b + 4 * SSTR + 4];
            }
            uint32_t bh[4][2], bl[4][2];
            #pragma unroll
            for (int j = 0; j < 4; j++) {
                const int n = nw * 32 + j * 8 + (lane >> 2);
                const int b = ((n * SSTR + k0) >> 1) + (lane & 3);
                bh[j][0] = BHu[b];
                bh[j][1] = BHu[b + 4];
                bl[j][0] = BLu[b];
                bl[j][1] = BLu[b + 4];
            }
            #pragma unroll
            for (int j = 0; j < 4; j++) {
                mma_bf16(acc[0][j], ah[0], bh[j]);
                mma_bf16(acc[1][j], ah[1], bh[j]);
            }
            #pragma unroll
            for (int j = 0; j < 4; j++) {
                mma_bf16(acc[0][j], al[0], bh[j]);
                mma_bf16(acc[1][j], al[1], bh[j]);
            }
            #pragma unroll
            for (int j = 0; j < 4; j++) {
                mma_bf16(acc[0][j], ah[0], bl[j]);
                mma_bf16(acc[1][j], ah[1], bl[j]);
            }
        }

        // epilogue
        #pragma unroll
        for (int mt = 0; mt < 2; mt++) {
            #pragma unroll
            for (int half = 0; half < 2; half++) {
                const int r = row0 + mw * 32 + mt * 16 + (lane >> 2) + half * 8;
                if (r < R) {
                    #pragma unroll
                    for (int j = 0; j < 4; j++) {
                        const int col = nt * 128 + nw * 32 + j * 8 + 2 * (lane & 3);
                        float2 o;
                        o.x = acc[mt][j][half * 2 + 0];
                        o.y = acc[mt][j][half * 2 + 1];
                        if (bias) { o.x += bias[col]; o.y += bias[col + 1]; }
                        const size_t yb = (size_t)r * ldy + col;
                        if (resid) { o.x += resid[yb]; o.y += resid[yb + 1]; }
                        *reinterpret_cast<float2 *>(Y + yb) = o;
                    }
                }
            }
        }
    }
}

// ======================= fused LN2 + MLP chain =============================
// smem: A hi/lo | H hi/lo | W double-buffer (hi/lo per buf)
#define C_AH 0
#define C_AL 34816
#define C_HH 69632
#define C_HL 104448
#define C_W0 139264
#define C_W1 176128
#define C_TOT 212992

__global__ void __launch_bounds__(512, 1) mlp_chain(
    float *__restrict__ Y,
    const float *__restrict__ lnw, const float *__restrict__ lnb,
    const __nv_bfloat16 *__restrict__ W1H, const __nv_bfloat16 *__restrict__ W1L,
    const __nv_bfloat16 *__restrict__ W2H, const __nv_bfloat16 *__restrict__ W2L,
    int R)
{
    extern __shared__ char smc[];
    uint32_t *AHu = reinterpret_cast<uint32_t *>(smc + C_AH);
    uint32_t *ALu = reinterpret_cast<uint32_t *>(smc + C_AL);
    uint32_t *HHu = reinterpret_cast<uint32_t *>(smc + C_HH);
    uint32_t *HLu = reinterpret_cast<uint32_t *>(smc + C_HL);
    char *w0h = smc + C_W0;             char *w0l = smc + C_W0 + 18432;
    char *w1h = smc + C_W1;             char *w1l = smc + C_W1 + 18432;
    uint32_t *W0H = reinterpret_cast<uint32_t *>(w0h);
    uint32_t *W0L = reinterpret_cast<uint32_t *>(w0l);
    uint32_t *W1Hs = reinterpret_cast<uint32_t *>(w1h);
    uint32_t *W1Ls = reinterpret_cast<uint32_t *>(w1l);

    const int tid  = threadIdx.x;
    const int wid  = tid >> 5;
    const int lane = tid & 31;
    const int mw   = wid & 3;
    const int nw   = wid >> 2;
    const int row0 = blockIdx.x * 128;

    // ---- A: load rows + LN2, split ---------------------------------------
    {
        const int r  = tid >> 2;
        const int c0 = (tid & 3) * 32;
        const int grow = row0 + r;
        const bool valid = grow < R;
        float4 v[8];
        if (valid) {
            const float4 *xr = reinterpret_cast<const float4 *>(
                Y + (size_t)grow * 128 + c0);
            #pragma unroll
            for (int i = 0; i < 8; i++) v[i] = xr[i];
        } else {
            #pragma unroll
            for (int i = 0; i < 8; i++) v[i] = make_float4(0.f, 0.f, 0.f, 0.f);
        }
        float s = 0.f, q = 0.f;
        #pragma unroll
        for (int i = 0; i < 8; i++) {
            s += v[i].x + v[i].y + v[i].z + v[i].w;
            q += v[i].x * v[i].x + v[i].y * v[i].y +
                 v[i].z * v[i].z + v[i].w * v[i].w;
        }
        s += __shfl_xor_sync(0xffffffffu, s, 1);
        s += __shfl_xor_sync(0xffffffffu, s, 2);
        q += __shfl_xor_sync(0xffffffffu, q, 1);
        q += __shfl_xor_sync(0xffffffffu, q, 2);
        const float m  = s * (1.f / 128.f);
        const float rs = rsqrtf(q * (1.f / 128.f) - m * m + 1e-5f);
        #pragma unroll
        for (int i = 0; i < 8; i++) {
            const int gc = c0 + 4 * i;
            v[i].x = (v[i].x - m) * rs * lnw[gc + 0] + lnb[gc + 0];
            v[i].y = (v[i].y - m) * rs * lnw[gc + 1] + lnb[gc + 1];
            v[i].z = (v[i].z - m) * rs * lnw[gc + 2] + lnb[gc + 2];
            v[i].w = (v[i].w - m) * rs * lnw[gc + 3] + lnb[gc + 3];
        }
        #pragma unroll
        for (int i = 0; i < 8; i++) {
            const int idx = (r * SSTR + c0 + 4 * i) >> 1;
            uint32_t h0, l0, h1, l1;
            split2(v[i].x, v[i].y, h0, l0);
            split2(v[i].z, v[i].w, h1, l1);
            AHu[idx] = h0; AHu[idx + 1] = h1;
            ALu[idx] = l0; ALu[idx + 1] = l1;
        }
    }

    float acc1[2][4][4], acc2[2][4][4];
    #pragma unroll
    for (int mt = 0; mt < 2; mt++)
        #pragma unroll
        for (int j = 0; j < 4; j++)
            #pragma unroll
            for (int q = 0; q < 4; q++) { acc1[mt][j][q] = 0.f; acc2[mt][j][q] = 0.f; }

    auto storeH = [&](float a[2][4][4], uint32_t *DH, uint32_t *DL) {
        #pragma unroll
        for (int mt = 0; mt < 2; mt++)
            #pragma unroll
            for (int qh = 0; qh < 2; qh++)
                #pragma unroll
                for (int j = 0; j < 4; j++) {
                    const int rl = mw * 32 + mt * 16 + (lane >> 2) + qh * 8;
                    const int cl = nw * 32 + j * 8 + 2 * (lane & 3);
                    float x = a[mt][j][qh * 2 + 0];
                    float y = a[mt][j][qh * 2 + 1];
                    x = x / (1.f + __expf(-x));
                    y = y / (1.f + __expf(-y));
                    uint32_t h, l;
                    split2(x, y, h, l);
                    const int idx = (rl * SSTR + cl) >> 1;
                    DH[idx] = h; DL[idx] = l;
                }
    };
    auto zero1 = [&]() {
        #pragma unroll
        for (int mt = 0; mt < 2; mt++)
            #pragma unroll
            for (int j = 0; j < 4; j++)
                #pragma unroll
                for (int q = 0; q < 4; q++) acc1[mt][j][q] = 0.f;
    };

    // pipeline: 8 W tiles: W1(h0k0,h0k1,h1k0,h1k1), W2(k0,k64,k128,k192)
    loadW(w0h, w0l, W1H, W1L, 128, 0,   0,  tid); CP_COMMIT();
    __syncthreads();   // A ready for all warps

    loadW(w1h, w1l, W1H, W1L, 128, 0,   64, tid); CP_COMMIT();
    CP_WAIT(1); __syncthreads();
    mma_tile(acc1, AHu, ALu, 0, W0H, W0L, mw, nw, lane);          // t0
    __syncthreads();
    loadW(w0h, w0l, W1H, W1L, 128, 128, 0,  tid); CP_COMMIT();
    CP_WAIT(1); __syncthreads();
    mma_tile(acc1, AHu, ALu, 64, W1Hs, W1Ls, mw, nw, lane);       // t1
    __syncthreads();
    storeH(acc1, HHu, HLu);     // H0 -> H buffer
    zero1();
    loadW(w1h, w1l, W1H, W1L, 128, 128, 64, tid); CP_COMMIT();
    CP_WAIT(1); __syncthreads();
    mma_tile(acc1, AHu, ALu, 0, W0H, W0L, mw, nw, lane);          // t2
    __syncthreads();
    loadW(w0h, w0l, W2H, W2L, 256, 0, 0, tid); CP_COMMIT();
    CP_WAIT(1); __syncthreads();
    mma_tile(acc1, AHu, ALu, 64, W1Hs, W1Ls, mw, nw, lane);       // t3
    __syncthreads();            // all reads of A done
    storeH(acc1, AHu, ALu);     // H1 -> A buffer
    loadW(w1h, w1l, W2H, W2L, 256, 0, 64, tid); CP_COMMIT();
    CP_WAIT(1); __syncthreads();
    mma_tile(acc2, HHu, HLu, 0, W0H, W0L, mw, nw, lane);          // t4
    __syncthreads();
    loadW(w0h, w0l, W2H, W2L, 256, 0, 128, tid); CP_COMMIT();
    CP_WAIT(1); __syncthreads();
    mma_tile(acc2, HHu, HLu, 64, W1Hs, W1Ls, mw, nw, lane);       // t5
    __syncthreads();
    loadW(w1h, w1l, W2H, W2L, 256, 0, 192, tid); CP_COMMIT();
    CP_WAIT(1); __syncthreads();
    mma_tile(acc2, AHu, ALu, 0, W0H, W0L, mw, nw, lane);          // t6
    CP_WAIT(0); __syncthreads();
    mma_tile(acc2, AHu, ALu, 64, W1Hs, W1Ls, mw, nw, lane);       // t7

    // epilogue: + resid (re-read Y), in place
    #pragma unroll
    for (int mt = 0; mt < 2; mt++) {
        #pragma unroll
        for (int half = 0; half < 2; half++) {
            const int r = row0 + mw * 32 + mt * 16 + (lane >> 2) + half * 8;
            if (r < R) {
                #pragma unroll
                for (int j = 0; j < 4; j++) {
                    const int col = nw * 32 + j * 8 + 2 * (lane & 3);
                    const size_t yb = (size_t)r * 128 + col;
                    float2 o;
                    o.x = acc2[mt][j][half * 2 + 0] + Y[yb];
                    o.y = acc2[mt][j][half * 2 + 1] + Y[yb + 1];
                    *reinterpret_cast<float2 *>(Y + yb) = o;
                }
            }
        }
    }
}

// ======================= fused edge attention + Wo_e =======================
// smem: A hi/lo | W double-buffer
#define T_AH 0
#define T_AL 34816
#define T_W0 69632
#define T_W1 106496
#define T_TOT 143360

__global__ void __launch_bounds__(512, 1) attn_gemm(
    const float *__restrict__ P, const float *__restrict__ QKV,
    const int *__restrict__ src, const int *__restrict__ dst,
    const __nv_bfloat16 *__restrict__ WH, const __nv_bfloat16 *__restrict__ WL,
    const float *__restrict__ bias, const float *__restrict__ resid,
    float *__restrict__ wV, float *__restrict__ z,
    float *__restrict__ Y)
{
    extern __shared__ char smc[];
    uint32_t *AHu = reinterpret_cast<uint32_t *>(smc + T_AH);
    uint32_t *ALu = reinterpret_cast<uint32_t *>(smc + T_AL);
    char *w0h = smc + T_W0;  char *w0l = smc + T_W0 + 18432;
    char *w1h = smc + T_W1;  char *w1l = smc + T_W1 + 18432;
    uint32_t *W0H = reinterpret_cast<uint32_t *>(w0h);
    uint32_t *W0L = reinterpret_cast<uint32_t *>(w0l);
    uint32_t *W1Hs = reinterpret_cast<uint32_t *>(w1h);
    uint32_t *W1Ls = reinterpret_cast<uint32_t *>(w1l);

    const int tid  = threadIdx.x;
    const int wid  = tid >> 5;
    const int lane = tid & 31;
    const int mw   = wid & 3;
    const int nw   = wid >> 2;
    const int row0 = blockIdx.x * 128;

    // issue first W tile load immediately (independent of A phase)
    loadW(w0h, w0l, WH, WL, 128, 0, 0, tid);  CP_COMMIT();
    loadW(w1h, w1l, WH, WL, 128, 0, 64, tid); CP_COMMIT();

    // ---- A phase: per-edge attention, e_out straight into smem -----------
    {
        const int r  = tid >> 2;
        const int c0 = (tid & 3) * 32;
        const int e  = row0 + r;
        float4 eo[8];
        if (e < EE) {
            const int s = src[e];
            const int d = dst[e];
            const float4 *pr = reinterpret_cast<const float4 *>(P + (size_t)e * 128 + c0);
            const float4 *kr = reinterpret_cast<const float4 *>(QKV + (size_t)s * 384 + 128 + c0);
            const float4 *qr = reinterpret_cast<const float4 *>(QKV + (size_t)d * 384 + c0);
            float sA = 0.f, sB = 0.f;
            #pragma unroll
            for (int i = 0; i < 8; i++) {
                const float4 kv = kr[i];
                const float4 qv = qr[i];
                const float4 pv = pr[i];
                float4 t;
                t.x = CLIP5(kv.x * qv.x * 0.25f) * pv.x;
                t.y = CLIP5(kv.y * qv.y * 0.25f) * pv.y;
                t.z = CLIP5(kv.z * qv.z * 0.25f) * pv.z;
                t.w = CLIP5(kv.w * qv.w * 0.25f) * pv.w;
                eo[i] = t;
                const float ts = t.x + t.y + t.z + t.w;
                if (i < 4) sA += ts; else sB += ts;
            }
            const float wA = __expf(CLIP5(sA));
            const float wB = __expf(CLIP5(sB));
            const float4 *vr = reinterpret_cast<const float4 *>(QKV + (size_t)s * 384 + 256 + c0);
            float *wvp = wV + (size_t)d * 128 + c0;
            #pragma unroll
            for (int i = 0; i < 8; i++) {
                const float w = (i < 4) ? wA : wB;
                const float4 vv = vr[i];
                atomicAdd(wvp + 4 * i + 0, vv.x * w);
                atomicAdd(wvp + 4 * i + 1, vv.y * w);
                atomicAdd(wvp + 4 * i + 2, vv.z * w);
                atomicAdd(wvp + 4 * i + 3, vv.w * w);
            }
            atomicAdd(z + (size_t)d * 8 + (c0 >> 4), wA);
            atomicAdd(z + (size_t)d * 8 + (c0 >> 4) + 1, wB);
        } else {
            #pragma unroll
            for (int i = 0; i < 8; i++) eo[i] = make_float4(0.f, 0.f, 0.f, 0.f);
        }
        #pragma unroll
        for (int i = 0; i < 8; i++) {
            const int idx = (r * SSTR + c0 + 4 * i) >> 1;
            uint32_t h0, l0, h1, l1;
            split2(eo[i].x, eo[i].y, h0, l0);
            split2(eo[i].z, eo[i].w, h1, l1);
            AHu[idx] = h0; AHu[idx + 1] = h1;
            ALu[idx] = l0; ALu[idx + 1] = l1;
        }
    }

    float acc[2][4][4];
    #pragma unroll
    for (int mt = 0; mt < 2; mt++)
        #pragma unroll
        for (int j = 0; j < 4; j++)
            #pragma unroll
            for (int q = 0; q < 4; q++) acc[mt][j][q] = 0.f;

    CP_WAIT(1); __syncthreads();
    mma_tile(acc, AHu, ALu, 0, W0H, W0L, mw, nw, lane);
    CP_WAIT(0); __syncthreads();
    mma_tile(acc, AHu, ALu, 64, W1Hs, W1Ls, mw, nw, lane);

    // epilogue: bias + resid(edge feats) -> Y
    #pragma unroll
    for (int mt = 0; mt < 2; mt++) {
        #pragma unroll
        for (int half = 0; half < 2; half++) {
            const int r = row0 + mw * 32 + mt * 16 + (lane >> 2) + half * 8;
            if (r < EE) {
                #pragma unroll
                for (int j = 0; j < 4; j++) {
                    const int col = nw * 32 + j * 8 + 2 * (lane & 3);
                    const size_t yb = (size_t)r * 128 + col;
                    float2 o;
                    o.x = acc[mt][j][half * 2 + 0] + bias[col] + resid[yb];
                    o.y = acc[mt][j][half * 2 + 1] + bias[col + 1] + resid[yb + 1];
                    *reinterpret_cast<float2 *>(Y + yb) = o;
                }
            }
        }
    }
}

// ---------------------------------------------------------------------------
__global__ void split_w(const float *__restrict__ W,
                        __nv_bfloat16 *__restrict__ H,
                        __nv_bfloat16 *__restrict__ L, int K, int No)
{
    const int i = blockIdx.x * 256 + threadIdx.x;
    if (i < K * No) {
        const int k = i / No;
        const int n = i - k * No;
        const float v = W[i];
        const __nv_bfloat16 h = __float2bfloat16(v);
        H[(size_t)n * K + k] = h;
        L[(size_t)n * K + k] = __float2bfloat16(v - __bfloat162float(h));
    }
}

__global__ void pack_bias(const float *__restrict__ a, const float *__restrict__ b,
                          const float *__restrict__ c, float *__restrict__ o)
{
    const int i = threadIdx.x;
    if (i < 128) { o[i] = a[i]; o[128 + i] = b[i]; o[256 + i] = c[i]; }
}

// ---------------------------------------------------------------------------
extern "C" void kernel_launch(void *const *d_in, const int *in_sizes, int n_in,
                              void *d_out, int out_size)
{
    const float *node   = (const float *)d_in[0];
    const float *edge   = (const float *)d_in[1];
    const int   *src    = (const int *)d_in[2];
    const int   *dst    = (const int *)d_in[3];
    const float *ln1n_w = (const float *)d_in[4];
    const float *ln1n_b = (const float *)d_in[5];
    const float *ln1e_w = (const float *)d_in[6];
    const float *ln1e_b = (const float *)d_in[7];
    const float *ln2n_w = (const float *)d_in[8];
    const float *ln2n_b = (const float *)d_in[9];
    const float *ln2e_w = (const float *)d_in[10];
    const float *ln2e_b = (const float *)d_in[11];
    const float *Wq = (const float *)d_in[12];  const float *bq = (const float *)d_in[13];
    const float *Wk = (const float *)d_in[14];  const float *bk = (const float *)d_in[15];
    const float *Wv = (const float *)d_in[16];  const float *bv = (const float *)d_in[17];
    const float *We = (const float *)d_in[18];  const float *be = (const float *)d_in[19];
    const float *Wo_n = (const float *)d_in[20]; const float *bo_n = (const float *)d_in[21];
    const float *Wo_e = (const float *)d_in[22]; const float *bo_e = (const float *)d_in[23];
    const float *w1n = (const float *)d_in[24];
    const float *w2n = (const float *)d_in[25];
    const float *w1e = (const float *)d_in[26];
    const float *w2e = (const float *)d_in[27];

    float *outh = (float *)d_out;
    float *oute = outh + (size_t)NN * DD;

    float *QKVp, *Pp, *wVp, *zp, *bqkv;
    __nv_bfloat16 *WHp, *WLp;
    cudaGetSymbolAddress((void **)&QKVp, g_QKV);
    cudaGetSymbolAddress((void **)&Pp,  g_P);
    cudaGetSymbolAddress((void **)&wVp, g_wV);
    cudaGetSymbolAddress((void **)&zp,  g_z);
    cudaGetSymbolAddress((void **)&bqkv, g_bqkv);
    cudaGetSymbolAddress((void **)&WHp, g_WH);
    cudaGetSymbolAddress((void **)&WLp, g_WL);

    cudaFuncSetAttribute(tcgemm,    cudaFuncAttributeMaxDynamicSharedMemorySize, G_TOT);
    cudaFuncSetAttribute(mlp_chain, cudaFuncAttributeMaxDynamicSharedMemorySize, C_TOT);
    cudaFuncSetAttribute(attn_gemm, cudaFuncAttributeMaxDynamicSharedMemorySize, T_TOT);

    // weight pre-split (tiny)
    auto SW = [&](const float *W, int ofs, int K, int No) {
        split_w<<<(K * No + 255) / 256, 256>>>(W, WHp + ofs, WLp + ofs, K, No);
    };
    SW(Wq, OF_QKV, 128, 128);
    SW(Wk, OF_QKV + 128 * 128, 128, 128);
    SW(Wv, OF_QKV + 256 * 128, 128, 128);
    SW(We, OF_WE, 128, 128);
    SW(Wo_n, OF_WON, 128, 128);
    SW(Wo_e, OF_WOE, 128, 128);
    SW(w1n, OF_W1N, 128, 256);
    SW(w2n, OF_W2N, 256, 128);
    SW(w1e, OF_W1E, 128, 256);
    SW(w2e, OF_W2E, 256, 128);
    pack_bias<<<1, 128>>>(bq, bk, bv, bqkv);

    cudaMemsetAsync(wVp, 0, (size_t)NN * DD * sizeof(float), 0);
    cudaMemsetAsync(zp,  0, (size_t)NN * HH * sizeof(float), 0);

    const int GN = (NN + 127) / 128;
    const int GE = (EE + 127) / 128;

    // LN1 + fused QKV projection (No=384); LN1 + edge projection -> P
    tcgemm<<<GN, 512, G_TOT>>>(node, 128, ln1n_w, ln1n_b, nullptr,
                               WHp + OF_QKV, WLp + OF_QKV, 384, bqkv, nullptr,
                               QKVp, 384, NN);
    tcgemm<<<GE, 512, G_TOT>>>(edge, 128, ln1e_w, ln1e_b, nullptr,
                               WHp + OF_WE, WLp + OF_WE, 128, be, nullptr,
                               Pp, 128, EE);

    // fused edge attention + Wo_e + resid -> oute (also scatters wV, z)
    attn_gemm<<<GE, 512, T_TOT>>>(Pp, QKVp, src, dst,
                                  WHp + OF_WOE, WLp + OF_WOE, bo_e, edge,
                                  wVp, zp, oute);

    // node output projection: A = wV / z, + resid -> outh
    tcgemm<<<GN, 512, G_TOT>>>(wVp, 128, nullptr, nullptr, zp,
                               WHp + OF_WON, WLp + OF_WON, 128, bo_n, node,
                               outh, 128, NN);

    // fused LN2 + MLP + resid, in place
    mlp_chain<<<GN, 512, C_TOT>>>(outh, ln2n_w, ln2n_b,
                                  WHp + OF_W1N, WLp + OF_W1N,
                                  WHp + OF_W2N, WLp + OF_W2N, NN);
    mlp_chain<<<GE, 512, C_TOT>>>(oute, ln2e_w, ln2e_b,
                                  WHp + OF_W1E, WLp + OF_W1E,
                                  WHp + OF_W2E, WLp + OF_W2E, EE);
}

// round 6
// speedup vs baseline: 1.8874x; 1.0065x over previous
#include <cuda_runtime.h>
#include <cuda_bf16.h>
#include <cstdint>

#define NN 50000
#define EE 800000
#define DD 128
#define HH 8

// ---------------- scratch (static device arrays; no allocation) ------------
__device__ float g_QKV[(size_t)NN * 384];
__device__ float g_P [(size_t)EE * DD];      // proj_e
__device__ float g_wV[(size_t)NN * DD];
__device__ float g_z [(size_t)NN * HH];
__device__ float g_bqkv[384];

// pre-split weights: bf16 hi/lo, [n][k] layout, packed in one buffer
#define OF_QKV  0                      // 384 x 128
#define OF_WE   49152                  // 128 x 128
#define OF_WON  65536
#define OF_WOE  81920
#define OF_W1N  98304                  // 256 x 128
#define OF_W2N  131072                 // 128 x 256
#define OF_W1E  163840
#define OF_W2E  196608
#define W_TOT   229376
__device__ __nv_bfloat16 g_WH[W_TOT];
__device__ __nv_bfloat16 g_WL[W_TOT];

// =================== helpers ===============================================
__device__ __forceinline__ void mma_bf16(float *c, const uint32_t *a,
                                         const uint32_t *b) {
    asm volatile(
        "mma.sync.aligned.m16n8k16.row.col.f32.bf16.bf16.f32 "
        "{%0,%1,%2,%3}, {%4,%5,%6,%7}, {%8,%9}, {%0,%1,%2,%3};"
        : "+f"(c[0]), "+f"(c[1]), "+f"(c[2]), "+f"(c[3])
        : "r"(a[0]), "r"(a[1]), "r"(a[2]), "r"(a[3]), "r"(b[0]), "r"(b[1]));
}
__device__ __forceinline__ void ldsm4(uint32_t *r, uint32_t addr) {
    asm volatile("ldmatrix.sync.aligned.m8n8.x4.shared.b16 {%0,%1,%2,%3}, [%4];"
                 : "=r"(r[0]), "=r"(r[1]), "=r"(r[2]), "=r"(r[3]) : "r"(addr));
}
__device__ __forceinline__ uint32_t pack_bf2(float x, float y) {
    __nv_bfloat162 t = __floats2bfloat162_rn(x, y);
    return *reinterpret_cast<uint32_t *>(&t);
}
__device__ __forceinline__ void split2(float x, float y, uint32_t &h, uint32_t &l) {
    __nv_bfloat16 hx = __float2bfloat16(x);
    __nv_bfloat16 hy = __float2bfloat16(y);
    float lx = x - __bfloat162float(hx);
    float ly = y - __bfloat162float(hy);
    __nv_bfloat162 hp; hp.x = hx; hp.y = hy;
    h = *reinterpret_cast<uint32_t *>(&hp);
    l = pack_bf2(lx, ly);
}
__device__ __forceinline__ void cp16(uint32_t saddr, const void *g) {
    asm volatile("cp.async.cg.shared.global [%0], [%1], 16;"
                 :: "r"(saddr), "l"(g));
}
#define CP_COMMIT() asm volatile("cp.async.commit_group;" ::: "memory")
#define CP_WAIT(n)  asm volatile("cp.async.wait_group %0;" :: "n"(n) : "memory")
#define CLIP5(x) fminf(fmaxf((x), -5.f), 5.f)

// A-style smem stride (bf16), W-buffer stride (bf16, for 64-k tiles)
#define SSTR 136
#define WSTR 72

// one 128x128(A) x [128n x 64k](B) MMA pass, 3-term bf16 split, ldmatrix loads
__device__ __forceinline__ void mma_tile(
    float acc[2][4][4],
    const char *AH, const char *AL, int kbase,
    const char *BH, const char *BL,
    int mw, int nw, int lane)
{
    const uint32_t aoff = (uint32_t)(((mw * 32 + (lane & 15)) * SSTR +
                                      kbase + (lane >> 4) * 8) * 2);
    const uint32_t boff = (uint32_t)(((nw * 32 + ((lane >> 4) & 1) * 8 + (lane & 7)) * WSTR +
                                      ((lane >> 3) & 1) * 8) * 2);
    const uint32_t aHb = (uint32_t)__cvta_generic_to_shared(AH) + aoff;
    const uint32_t aLb = (uint32_t)__cvta_generic_to_shared(AL) + aoff;
    const uint32_t bHb = (uint32_t)__cvta_generic_to_shared(BH) + boff;
    const uint32_t bLb = (uint32_t)__cvta_generic_to_shared(BL) + boff;

    #pragma unroll
    for (int kk = 0; kk < 4; kk++) {
        const uint32_t ka = kk * 32;   // 16 elements = 32 bytes
        uint32_t ah[2][4], al[2][4], bh[2][4], bl[2][4];
        ldsm4(ah[0], aHb + ka);
        ldsm4(ah[1], aHb + ka + 16 * SSTR * 2);
        ldsm4(al[0], aLb + ka);
        ldsm4(al[1], aLb + ka + 16 * SSTR * 2);
        ldsm4(bh[0], bHb + ka);
        ldsm4(bh[1], bHb + ka + 16 * WSTR * 2);
        ldsm4(bl[0], bLb + ka);
        ldsm4(bl[1], bLb + ka + 16 * WSTR * 2);
        #pragma unroll
        for (int j = 0; j < 4; j++) {
            const uint32_t *bp = &bh[j >> 1][2 * (j & 1)];
            mma_bf16(acc[0][j], ah[0], bp);
            mma_bf16(acc[1][j], ah[1], bp);
        }
        #pragma unroll
        for (int j = 0; j < 4; j++) {
            const uint32_t *bp = &bh[j >> 1][2 * (j & 1)];
            mma_bf16(acc[0][j], al[0], bp);
            mma_bf16(acc[1][j], al[1], bp);
        }
        #pragma unroll
        for (int j = 0; j < 4; j++) {
            const uint32_t *bp = &bl[j >> 1][2 * (j & 1)];
            mma_bf16(acc[0][j], ah[0], bp);
            mma_bf16(acc[1][j], ah[1], bp);
        }
    }
}

// cp.async load of a [128n x 64k] hi/lo W tile into a WSTR-strided buffer
__device__ __forceinline__ void loadW(
    char *smem_hi, char *smem_lo,
    const __nv_bfloat16 *WH, const __nv_bfloat16 *WL,
    int Kw, int nrow_base, int kofs, int tid)
{
    const int n = tid >> 2;
    const int q = (tid & 3) * 16;
    const size_t g = (size_t)(nrow_base + n) * Kw + kofs + q;
    const uint32_t dh = (uint32_t)__cvta_generic_to_shared(smem_hi + (n * WSTR + q) * 2);
    const uint32_t dl = (uint32_t)__cvta_generic_to_shared(smem_lo + (n * WSTR + q) * 2);
    cp16(dh, WH + g);
    cp16(dh + 16, WH + g + 8);
    cp16(dl, WL + g);
    cp16(dl + 16, WL + g + 8);
}

// ======================= generic pipelined GEMM ============================
// smem: A hi/lo | 2 W slots (hi+lo each)
#define G_AH 0
#define G_AL 34816
#define G_W  69632
#define G_SLOT 36864
#define G_TOT (G_W + 2 * G_SLOT)   // 143360

__global__ void __launch_bounds__(512, 1) tcgemm(
    const float *__restrict__ X, int ldx,
    const float *__restrict__ lnw, const float *__restrict__ lnb,
    const float *__restrict__ zdiv,
    const __nv_bfloat16 *__restrict__ WH, const __nv_bfloat16 *__restrict__ WL,
    int No, const float *__restrict__ bias, const float *__restrict__ resid,
    float *__restrict__ Y, int ldy, int R)
{
    extern __shared__ char smc[];
    char *AHc = smc + G_AH;
    char *ALc = smc + G_AL;
    uint32_t *AHu = reinterpret_cast<uint32_t *>(AHc);
    uint32_t *ALu = reinterpret_cast<uint32_t *>(ALc);

    const int tid  = threadIdx.x;
    const int wid  = tid >> 5;
    const int lane = tid & 31;
    const int mw   = wid & 3;
    const int nw   = wid >> 2;
    const int row0 = blockIdx.x * 128;
    const bool do_ln = (lnw != nullptr);
    const int T = (No >> 7) * 2;       // 64-k tiles

    // prologue: prefetch tiles 0 and 1 (nt0/k0, nt0/k64)
    loadW(smc + G_W, smc + G_W + 18432, WH, WL, 128, 0, 0, tid); CP_COMMIT();
    loadW(smc + G_W + G_SLOT, smc + G_W + G_SLOT + 18432, WH, WL, 128, 0, 64, tid); CP_COMMIT();

    // ---- A: load rows, optional z-normalize / LN, split to bf16 ----------
    {
        const int r  = tid >> 2;
        const int c0 = (tid & 3) * 32;
        const int grow = row0 + r;
        const bool valid = grow < R;
        float4 v[8];
        if (valid) {
            const float4 *xr = reinterpret_cast<const float4 *>(
                X + (size_t)grow * ldx + c0);
            #pragma unroll
            for (int i = 0; i < 8; i++) v[i] = xr[i];
        } else {
            #pragma unroll
            for (int i = 0; i < 8; i++) v[i] = make_float4(0.f, 0.f, 0.f, 0.f);
        }
        if (zdiv && valid) {
            const float rA = 1.f / (zdiv[(size_t)grow * 8 + (c0 >> 4)] + 1e-8f);
            const float rB = 1.f / (zdiv[(size_t)grow * 8 + (c0 >> 4) + 1] + 1e-8f);
            #pragma unroll
            for (int i = 0; i < 8; i++) {
                const float s = (i < 4) ? rA : rB;
                v[i].x *= s; v[i].y *= s; v[i].z *= s; v[i].w *= s;
            }
        }
        if (do_ln) {
            float s = 0.f, q = 0.f;
            #pragma unroll
            for (int i = 0; i < 8; i++) {
                s += v[i].x + v[i].y + v[i].z + v[i].w;
                q += v[i].x * v[i].x + v[i].y * v[i].y +
                     v[i].z * v[i].z + v[i].w * v[i].w;
            }
            s += __shfl_xor_sync(0xffffffffu, s, 1);
            s += __shfl_xor_sync(0xffffffffu, s, 2);
            q += __shfl_xor_sync(0xffffffffu, q, 1);
            q += __shfl_xor_sync(0xffffffffu, q, 2);
            const float m  = s * (1.f / 128.f);
            const float rs = rsqrtf(q * (1.f / 128.f) - m * m + 1e-5f);
            #pragma unroll
            for (int i = 0; i < 8; i++) {
                const int gc = c0 + 4 * i;
                v[i].x = (v[i].x - m) * rs * lnw[gc + 0] + lnb[gc + 0];
                v[i].y = (v[i].y - m) * rs * lnw[gc + 1] + lnb[gc + 1];
                v[i].z = (v[i].z - m) * rs * lnw[gc + 2] + lnb[gc + 2];
                v[i].w = (v[i].w - m) * rs * lnw[gc + 3] + lnb[gc + 3];
            }
        }
        #pragma unroll
        for (int i = 0; i < 8; i++) {
            const int idx = (r * SSTR + c0 + 4 * i) >> 1;
            uint32_t h0, l0, h1, l1;
            split2(v[i].x, v[i].y, h0, l0);
            split2(v[i].z, v[i].w, h1, l1);
            AHu[idx] = h0; AHu[idx + 1] = h1;
            ALu[idx] = l0; ALu[idx + 1] = l1;
        }
    }

    float acc[2][4][4];
    for (int t = 0; t < T; t++) {
        const int nt = t >> 1;
        if (!(t & 1)) {
            #pragma unroll
            for (int mt = 0; mt < 2; mt++)
                #pragma unroll
                for (int j = 0; j < 4; j++)
                    #pragma unroll
                    for (int q = 0; q < 4; q++) acc[mt][j][q] = 0.f;
        }
        if (t < T - 1) { CP_WAIT(1); } else { CP_WAIT(0); }
        __syncthreads();
        char *sh = smc + G_W + (t & 1) * G_SLOT;
        mma_tile(acc, AHc, ALc, (t & 1) * 64, sh, sh + 18432, mw, nw, lane);
        __syncthreads();
        if (t + 2 < T) {
            loadW(sh, sh + 18432, WH, WL, 128, ((t + 2) >> 1) * 128,
                  ((t + 2) & 1) * 64, tid);
            CP_COMMIT();
        }
        if (t & 1) {
            #pragma unroll
            for (int mt = 0; mt < 2; mt++) {
                #pragma unroll
                for (int half = 0; half < 2; half++) {
                    const int r = row0 + mw * 32 + mt * 16 + (lane >> 2) + half * 8;
                    if (r < R) {
                        #pragma unroll
                        for (int j = 0; j < 4; j++) {
                            const int col = nt * 128 + nw * 32 + j * 8 + 2 * (lane & 3);
                            float2 o;
                            o.x = acc[mt][j][half * 2 + 0];
                            o.y = acc[mt][j][half * 2 + 1];
                            if (bias) { o.x += bias[col]; o.y += bias[col + 1]; }
                            const size_t yb = (size_t)r * ldy + col;
                            if (resid) { o.x += resid[yb]; o.y += resid[yb + 1]; }
                            *reinterpret_cast<float2 *>(Y + yb) = o;
                        }
                    }
                }
            }
        }
    }
}

// ======================= fused LN2 + MLP chain =============================
#define C_AH 0
#define C_AL 34816
#define C_HH 69632
#define C_HL 104448
#define C_W0 139264
#define C_W1 176128
#define C_TOT 212992

__global__ void __launch_bounds__(512, 1) mlp_chain(
    float *__restrict__ Y,
    const float *__restrict__ lnw, const float *__restrict__ lnb,
    const __nv_bfloat16 *__restrict__ W1H, const __nv_bfloat16 *__restrict__ W1L,
    const __nv_bfloat16 *__restrict__ W2H, const __nv_bfloat16 *__restrict__ W2L,
    int R)
{
    extern __shared__ char smc[];
    char *AHc = smc + C_AH;  char *ALc = smc + C_AL;
    char *HHc = smc + C_HH;  char *HLc = smc + C_HL;
    uint32_t *AHu = reinterpret_cast<uint32_t *>(AHc);
    uint32_t *ALu = reinterpret_cast<uint32_t *>(ALc);
    uint32_t *HHu = reinterpret_cast<uint32_t *>(HHc);
    uint32_t *HLu = reinterpret_cast<uint32_t *>(HLc);
    char *w0h = smc + C_W0;  char *w0l = smc + C_W0 + 18432;
    char *w1h = smc + C_W1;  char *w1l = smc + C_W1 + 18432;

    const int tid  = threadIdx.x;
    const int wid  = tid >> 5;
    const int lane = tid & 31;
    const int mw   = wid & 3;
    const int nw   = wid >> 2;
    const int row0 = blockIdx.x * 128;

    loadW(w0h, w0l, W1H, W1L, 128, 0, 0, tid); CP_COMMIT();
    loadW(w1h, w1l, W1H, W1L, 128, 0, 64, tid); CP_COMMIT();

    // ---- A: load rows + LN2, split ---------------------------------------
    {
        const int r  = tid >> 2;
        const int c0 = (tid & 3) * 32;
        const int grow = row0 + r;
        const bool valid = grow < R;
        float4 v[8];
        if (valid) {
            const float4 *xr = reinterpret_cast<const float4 *>(
                Y + (size_t)grow * 128 + c0);
            #pragma unroll
            for (int i = 0; i < 8; i++) v[i] = xr[i];
        } else {
            #pragma unroll
            for (int i = 0; i < 8; i++) v[i] = make_float4(0.f, 0.f, 0.f, 0.f);
        }
        float s = 0.f, q = 0.f;
        #pragma unroll
        for (int i = 0; i < 8; i++) {
            s += v[i].x + v[i].y + v[i].z + v[i].w;
            q += v[i].x * v[i].x + v[i].y * v[i].y +
                 v[i].z * v[i].z + v[i].w * v[i].w;
        }
        s += __shfl_xor_sync(0xffffffffu, s, 1);
        s += __shfl_xor_sync(0xffffffffu, s, 2);
        q += __shfl_xor_sync(0xffffffffu, q, 1);
        q += __shfl_xor_sync(0xffffffffu, q, 2);
        const float m  = s * (1.f / 128.f);
        const float rs = rsqrtf(q * (1.f / 128.f) - m * m + 1e-5f);
        #pragma unroll
        for (int i = 0; i < 8; i++) {
            const int gc = c0 + 4 * i;
            v[i].x = (v[i].x - m) * rs * lnw[gc + 0] + lnb[gc + 0];
            v[i].y = (v[i].y - m) * rs * lnw[gc + 1] + lnb[gc + 1];
            v[i].z = (v[i].z - m) * rs * lnw[gc + 2] + lnb[gc + 2];
            v[i].w = (v[i].w - m) * rs * lnw[gc + 3] + lnb[gc + 3];
        }
        #pragma unroll
        for (int i = 0; i < 8; i++) {
            const int idx = (r * SSTR + c0 + 4 * i) >> 1;
            uint32_t h0, l0, h1, l1;
            split2(v[i].x, v[i].y, h0, l0);
            split2(v[i].z, v[i].w, h1, l1);
            AHu[idx] = h0; AHu[idx + 1] = h1;
            ALu[idx] = l0; ALu[idx + 1] = l1;
        }
    }

    float acc1[2][4][4], acc2[2][4][4];
    #pragma unroll
    for (int mt = 0; mt < 2; mt++)
        #pragma unroll
        for (int j = 0; j < 4; j++)
            #pragma unroll
            for (int q = 0; q < 4; q++) { acc1[mt][j][q] = 0.f; acc2[mt][j][q] = 0.f; }

    auto storeH = [&](float a[2][4][4], uint32_t *DH, uint32_t *DL) {
        #pragma unroll
        for (int mt = 0; mt < 2; mt++)
            #pragma unroll
            for (int qh = 0; qh < 2; qh++)
                #pragma unroll
                for (int j = 0; j < 4; j++) {
                    const int rl = mw * 32 + mt * 16 + (lane >> 2) + qh * 8;
                    const int cl = nw * 32 + j * 8 + 2 * (lane & 3);
                    float x = a[mt][j][qh * 2 + 0];
                    float y = a[mt][j][qh * 2 + 1];
                    x = x / (1.f + __expf(-x));
                    y = y / (1.f + __expf(-y));
                    uint32_t h, l;
                    split2(x, y, h, l);
                    const int idx = (rl * SSTR + cl) >> 1;
                    DH[idx] = h; DL[idx] = l;
                }
    };
    auto zero1 = [&]() {
        #pragma unroll
        for (int mt = 0; mt < 2; mt++)
            #pragma unroll
            for (int j = 0; j < 4; j++)
                #pragma unroll
                for (int q = 0; q < 4; q++) acc1[mt][j][q] = 0.f;
    };

    __syncthreads();   // A ready
    CP_WAIT(1); __syncthreads();
    mma_tile(acc1, AHc, ALc, 0, w0h, w0l, mw, nw, lane);          // W1 h0 k0
    __syncthreads();
    loadW(w0h, w0l, W1H, W1L, 128, 128, 0, tid); CP_COMMIT();
    CP_WAIT(1); __syncthreads();
    mma_tile(acc1, AHc, ALc, 64, w1h, w1l, mw, nw, lane);         // W1 h0 k64
    __syncthreads();
    storeH(acc1, HHu, HLu);
    zero1();
    loadW(w1h, w1l, W1H, W1L, 128, 128, 64, tid); CP_COMMIT();
    CP_WAIT(1); __syncthreads();
    mma_tile(acc1, AHc, ALc, 0, w0h, w0l, mw, nw, lane);          // W1 h1 k0
    __syncthreads();
    loadW(w0h, w0l, W2H, W2L, 256, 0, 0, tid); CP_COMMIT();
    CP_WAIT(1); __syncthreads();
    mma_tile(acc1, AHc, ALc, 64, w1h, w1l, mw, nw, lane);         // W1 h1 k64
    __syncthreads();            // all reads of A done
    storeH(acc1, AHu, ALu);     // H1 -> A buffer
    loadW(w1h, w1l, W2H, W2L, 256, 0, 64, tid); CP_COMMIT();
    CP_WAIT(1); __syncthreads();
    mma_tile(acc2, HHc, HLc, 0, w0h, w0l, mw, nw, lane);          // W2 k0
    __syncthreads();
    loadW(w0h, w0l, W2H, W2L, 256, 0, 128, tid); CP_COMMIT();
    CP_WAIT(1); __syncthreads();
    mma_tile(acc2, HHc, HLc, 64, w1h, w1l, mw, nw, lane);         // W2 k64
    __syncthreads();
    loadW(w1h, w1l, W2H, W2L, 256, 0, 192, tid); CP_COMMIT();
    CP_WAIT(1); __syncthreads();
    mma_tile(acc2, AHc, ALc, 0, w0h, w0l, mw, nw, lane);          // W2 k128
    CP_WAIT(0); __syncthreads();
    mma_tile(acc2, AHc, ALc, 64, w1h, w1l, mw, nw, lane);         // W2 k192

    #pragma unroll
    for (int mt = 0; mt < 2; mt++) {
        #pragma unroll
        for (int half = 0; half < 2; half++) {
            const int r = row0 + mw * 32 + mt * 16 + (lane >> 2) + half * 8;
            if (r < R) {
                #pragma unroll
                for (int j = 0; j < 4; j++) {
                    const int col = nw * 32 + j * 8 + 2 * (lane & 3);
                    const size_t yb = (size_t)r * 128 + col;
                    float2 o;
                    o.x = acc2[mt][j][half * 2 + 0] + Y[yb];
                    o.y = acc2[mt][j][half * 2 + 1] + Y[yb + 1];
                    *reinterpret_cast<float2 *>(Y + yb) = o;
                }
            }
        }
    }
}

// ======================= fused edge attention + Wo_e =======================
#define T_AH 0
#define T_AL 34816
#define T_W0 69632
#define T_W1 106496
#define T_TOT 143360

__global__ void __launch_bounds__(512, 1) attn_gemm(
    const float *__restrict__ P, const float *__restrict__ QKV,
    const int *__restrict__ src, const int *__restrict__ dst,
    const __nv_bfloat16 *__restrict__ WH, const __nv_bfloat16 *__restrict__ WL,
    const float *__restrict__ bias, const float *__restrict__ resid,
    float *__restrict__ wV, float *__restrict__ z,
    float *__restrict__ Y)
{
    extern __shared__ char smc[];
    char *AHc = smc + T_AH;  char *ALc = smc + T_AL;
    uint32_t *AHu = reinterpret_cast<uint32_t *>(AHc);
    uint32_t *ALu = reinterpret_cast<uint32_t *>(ALc);
    char *w0h = smc + T_W0;  char *w0l = smc + T_W0 + 18432;
    char *w1h = smc + T_W1;  char *w1l = smc + T_W1 + 18432;

    const int tid  = threadIdx.x;
    const int wid  = tid >> 5;
    const int lane = tid & 31;
    const int mw   = wid & 3;
    const int nw   = wid >> 2;
    const int row0 = blockIdx.x * 128;

    loadW(w0h, w0l, WH, WL, 128, 0, 0, tid);  CP_COMMIT();
    loadW(w1h, w1l, WH, WL, 128, 0, 64, tid); CP_COMMIT();

    // ---- A phase: per-edge attention, e_out straight into smem -----------
    {
        const int r  = tid >> 2;
        const int c0 = (tid & 3) * 32;
        const int e  = row0 + r;
        float4 eo[8];
        if (e < EE) {
            const int s = src[e];
            const int d = dst[e];
            const float4 *pr = reinterpret_cast<const float4 *>(P + (size_t)e * 128 + c0);
            const float4 *kr = reinterpret_cast<const float4 *>(QKV + (size_t)s * 384 + 128 + c0);
            const float4 *qr = reinterpret_cast<const float4 *>(QKV + (size_t)d * 384 + c0);
            float sA = 0.f, sB = 0.f;
            #pragma unroll
            for (int i = 0; i < 8; i++) {
                const float4 kv = kr[i];
                const float4 qv = qr[i];
                const float4 pv = pr[i];
                float4 t;
                t.x = CLIP5(kv.x * qv.x * 0.25f) * pv.x;
                t.y = CLIP5(kv.y * qv.y * 0.25f) * pv.y;
                t.z = CLIP5(kv.z * qv.z * 0.25f) * pv.z;
                t.w = CLIP5(kv.w * qv.w * 0.25f) * pv.w;
                eo[i] = t;
                const float ts = t.x + t.y + t.z + t.w;
                if (i < 4) sA += ts; else sB += ts;
            }
            const float wA = __expf(CLIP5(sA));
            const float wB = __expf(CLIP5(sB));
            const float4 *vr = reinterpret_cast<const float4 *>(QKV + (size_t)s * 384 + 256 + c0);
            float *wvp = wV + (size_t)d * 128 + c0;
            #pragma unroll
            for (int i = 0; i < 8; i++) {
                const float w = (i < 4) ? wA : wB;
                const float4 vv = vr[i];
                atomicAdd(wvp + 4 * i + 0, vv.x * w);
                atomicAdd(wvp + 4 * i + 1, vv.y * w);
                atomicAdd(wvp + 4 * i + 2, vv.z * w);
                atomicAdd(wvp + 4 * i + 3, vv.w * w);
            }
            atomicAdd(z + (size_t)d * 8 + (c0 >> 4), wA);
            atomicAdd(z + (size_t)d * 8 + (c0 >> 4) + 1, wB);
        } else {
            #pragma unroll
            for (int i = 0; i < 8; i++) eo[i] = make_float4(0.f, 0.f, 0.f, 0.f);
        }
        #pragma unroll
        for (int i = 0; i < 8; i++) {
            const int idx = (r * SSTR + c0 + 4 * i) >> 1;
            uint32_t h0, l0, h1, l1;
            split2(eo[i].x, eo[i].y, h0, l0);
            split2(eo[i].z, eo[i].w, h1, l1);
            AHu[idx] = h0; AHu[idx + 1] = h1;
            ALu[idx] = l0; ALu[idx + 1] = l1;
        }
    }

    float acc[2][4][4];
    #pragma unroll
    for (int mt = 0; mt < 2; mt++)
        #pragma unroll
        for (int j = 0; j < 4; j++)
            #pragma unroll
            for (int q = 0; q < 4; q++) acc[mt][j][q] = 0.f;

    CP_WAIT(1); __syncthreads();
    mma_tile(acc, AHc, ALc, 0, w0h, w0l, mw, nw, lane);
    CP_WAIT(0); __syncthreads();
    mma_tile(acc, AHc, ALc, 64, w1h, w1l, mw, nw, lane);

    #pragma unroll
    for (int mt = 0; mt < 2; mt++) {
        #pragma unroll
        for (int half = 0; half < 2; half++) {
            const int r = row0 + mw * 32 + mt * 16 + (lane >> 2) + half * 8;
            if (r < EE) {
                #pragma unroll
                for (int j = 0; j < 4; j++) {
                    const int col = nw * 32 + j * 8 + 2 * (lane & 3);
                    const size_t yb = (size_t)r * 128 + col;
                    float2 o;
                    o.x = acc[mt][j][half * 2 + 0] + bias[col] + resid[yb];
                    o.y = acc[mt][j][half * 2 + 1] + bias[col + 1] + resid[yb + 1];
                    *reinterpret_cast<float2 *>(Y + yb) = o;
                }
            }
        }
    }
}

// ---------------------------------------------------------------------------
__global__ void split_w(const float *__restrict__ W,
                        __nv_bfloat16 *__restrict__ H,
                        __nv_bfloat16 *__restrict__ L, int K, int No)
{
    const int i = blockIdx.x * 256 + threadIdx.x;
    if (i < K * No) {
        const int k = i / No;
        const int n = i - k * No;
        const float v = W[i];
        const __nv_bfloat16 h = __float2bfloat16(v);
        H[(size_t)n * K + k] = h;
        L[(size_t)n * K + k] = __float2bfloat16(v - __bfloat162float(h));
    }
}

__global__ void pack_bias(const float *__restrict__ a, const float *__restrict__ b,
                          const float *__restrict__ c, float *__restrict__ o)
{
    const int i = threadIdx.x;
    if (i < 128) { o[i] = a[i]; o[128 + i] = b[i]; o[256 + i] = c[i]; }
}

// ---------------------------------------------------------------------------
extern "C" void kernel_launch(void *const *d_in, const int *in_sizes, int n_in,
                              void *d_out, int out_size)
{
    const float *node   = (const float *)d_in[0];
    const float *edge   = (const float *)d_in[1];
    const int   *src    = (const int *)d_in[2];
    const int   *dst    = (const int *)d_in[3];
    const float *ln1n_w = (const float *)d_in[4];
    const float *ln1n_b = (const float *)d_in[5];
    const float *ln1e_w = (const float *)d_in[6];
    const float *ln1e_b = (const float *)d_in[7];
    const float *ln2n_w = (const float *)d_in[8];
    const float *ln2n_b = (const float *)d_in[9];
    const float *ln2e_w = (const float *)d_in[10];
    const float *ln2e_b = (const float *)d_in[11];
    const float *Wq = (const float *)d_in[12];  const float *bq = (const float *)d_in[13];
    const float *Wk = (const float *)d_in[14];  const float *bk = (const float *)d_in[15];
    const float *Wv = (const float *)d_in[16];  const float *bv = (const float *)d_in[17];
    const float *We = (const float *)d_in[18];  const float *be = (const float *)d_in[19];
    const float *Wo_n = (const float *)d_in[20]; const float *bo_n = (const float *)d_in[21];
    const float *Wo_e = (const float *)d_in[22]; const float *bo_e = (const float *)d_in[23];
    const float *w1n = (const float *)d_in[24];
    const float *w2n = (const float *)d_in[25];
    const float *w1e = (const float *)d_in[26];
    const float *w2e = (const float *)d_in[27];

    float *outh = (float *)d_out;
    float *oute = outh + (size_t)NN * DD;

    float *QKVp, *Pp, *wVp, *zp, *bqkv;
    __nv_bfloat16 *WHp, *WLp;
    cudaGetSymbolAddress((void **)&QKVp, g_QKV);
    cudaGetSymbolAddress((void **)&Pp,  g_P);
    cudaGetSymbolAddress((void **)&wVp, g_wV);
    cudaGetSymbolAddress((void **)&zp,  g_z);
    cudaGetSymbolAddress((void **)&bqkv, g_bqkv);
    cudaGetSymbolAddress((void **)&WHp, g_WH);
    cudaGetSymbolAddress((void **)&WLp, g_WL);

    cudaFuncSetAttribute(tcgemm,    cudaFuncAttributeMaxDynamicSharedMemorySize, G_TOT);
    cudaFuncSetAttribute(mlp_chain, cudaFuncAttributeMaxDynamicSharedMemorySize, C_TOT);
    cudaFuncSetAttribute(attn_gemm, cudaFuncAttributeMaxDynamicSharedMemorySize, T_TOT);

    auto SW = [&](const float *W, int ofs, int K, int No) {
        split_w<<<(K * No + 255) / 256, 256>>>(W, WHp + ofs, WLp + ofs, K, No);
    };
    SW(Wq, OF_QKV, 128, 128);
    SW(Wk, OF_QKV + 128 * 128, 128, 128);
    SW(Wv, OF_QKV + 256 * 128, 128, 128);
    SW(We, OF_WE, 128, 128);
    SW(Wo_n, OF_WON, 128, 128);
    SW(Wo_e, OF_WOE, 128, 128);
    SW(w1n, OF_W1N, 128, 256);
    SW(w2n, OF_W2N, 256, 128);
    SW(w1e, OF_W1E, 128, 256);
    SW(w2e, OF_W2E, 256, 128);
    pack_bias<<<1, 128>>>(bq, bk, bv, bqkv);

    cudaMemsetAsync(wVp, 0, (size_t)NN * DD * sizeof(float), 0);
    cudaMemsetAsync(zp,  0, (size_t)NN * HH * sizeof(float), 0);

    const int GN = (NN + 127) / 128;
    const int GE = (EE + 127) / 128;

    // LN1 + fused QKV projection (No=384); LN1 + edge projection -> P
    tcgemm<<<GN, 512, G_TOT>>>(node, 128, ln1n_w, ln1n_b, nullptr,
                               WHp + OF_QKV, WLp + OF_QKV, 384, bqkv, nullptr,
                               QKVp, 384, NN);
    tcgemm<<<GE, 512, G_TOT>>>(edge, 128, ln1e_w, ln1e_b, nullptr,
                               WHp + OF_WE, WLp + OF_WE, 128, be, nullptr,
                               Pp, 128, EE);

    // fused edge attention + Wo_e + resid -> oute (also scatters wV, z)
    attn_gemm<<<GE, 512, T_TOT>>>(Pp, QKVp, src, dst,
                                  WHp + OF_WOE, WLp + OF_WOE, bo_e, edge,
                                  wVp, zp, oute);

    // node output projection: A = wV / z, + resid -> outh
    tcgemm<<<GN, 512, G_TOT>>>(wVp, 128, nullptr, nullptr, zp,
                               WHp + OF_WON, WLp + OF_WON, 128, bo_n, node,
                               outh, 128, NN);

    // fused LN2 + MLP + resid, in place
    mlp_chain<<<GN, 512, C_TOT>>>(outh, ln2n_w, ln2n_b,
                                  WHp + OF_W1N, WLp + OF_W1N,
                                  WHp + OF_W2N, WLp + OF_W2N, NN);
    mlp_chain<<<GE, 512, C_TOT>>>(oute, ln2e_w, ln2e_b,
                                  WHp + OF_W1E, WLp + OF_W1E,
                                  WHp + OF_W2E, WLp + OF_W2E, EE);
}